// round 1
// baseline (speedup 1.0000x reference)
#include <cuda_runtime.h>
#include <cstdint>

// ---------------------------------------------------------------------------
// Problem constants (fixed by the dataset)
// ---------------------------------------------------------------------------
#define NC_MAX 50000
#define NG_MAX 30000
#define FD 128

// Scratch layout (floats), all in one __device__ global:
//   [0)          Ycc / Zcc   : NC*128
//   [6.4M)       Ycg         : NC*128
//   [12.8M)      Ygc / Zgc   : NG*128
//   [16.64M)     aggCC       : NC*128
//   [23.04M)     aggGC       : NC*128
//   [29.44M)     aggCG       : NG*128
//   [33.28M)     h1_chem     : NC*128
//   [39.68M)     h1_gene     : NG*128
#define OFF_YCC   ((size_t)0)
#define OFF_YCG   ((size_t)NC_MAX * FD)
#define OFF_YGC   ((size_t)2 * NC_MAX * FD)
#define OFF_AGGCC ((size_t)2 * NC_MAX * FD + (size_t)NG_MAX * FD)
#define OFF_AGGGC (OFF_AGGCC + (size_t)NC_MAX * FD)
#define OFF_AGGCG (OFF_AGGGC + (size_t)NC_MAX * FD)
#define OFF_H1C   (OFF_AGGCG + (size_t)NG_MAX * FD)
#define OFF_H1G   (OFF_H1C + (size_t)NC_MAX * FD)
#define SCRATCH_FLOATS (OFF_H1G + (size_t)NG_MAX * FD)

__device__ float g_scratch[SCRATCH_FLOATS];

// Degree / inverse-sqrt-degree arrays (contiguous so one memset + one rsqrt pass)
#define DOFF_INVS_CC 0
#define DOFF_INVD_CC (DOFF_INVS_CC + NC_MAX)
#define DOFF_INVS_CG (DOFF_INVD_CC + NC_MAX)
#define DOFF_INVD_CG (DOFF_INVS_CG + NC_MAX)
#define DOFF_INVS_GC (DOFF_INVD_CG + NG_MAX)
#define DOFF_INVD_GC (DOFF_INVS_GC + NG_MAX)
#define DEG_TOTAL    (DOFF_INVD_GC + NC_MAX)

__device__ float g_deg[DEG_TOTAL];

// ---------------------------------------------------------------------------
// Kernels
// ---------------------------------------------------------------------------

__global__ void deg_kernel(const int* __restrict__ src, const int* __restrict__ dst,
                           float* degS, float* degD, int nE) {
    int i = blockIdx.x * blockDim.x + threadIdx.x;
    if (i < nE) {
        atomicAdd(&degS[src[i]], 1.0f);
        atomicAdd(&degD[dst[i]], 1.0f);
    }
}

__global__ void rsqrt_kernel(float* d, int n) {
    int i = blockIdx.x * blockDim.x + threadIdx.x;
    if (i < n) d[i] = rsqrtf(fmaxf(d[i], 1.0f));
}

// C[M,128] = A[M,128] @ B[128,128], fp32, classic 128x128x8 tile, 256 threads,
// 8x8 per-thread micro-tile.
__global__ __launch_bounds__(256) void sgemm128(const float* __restrict__ A,
                                                const float* __restrict__ B,
                                                float* __restrict__ C, int M) {
    const int K = 128, N = 128;
    __shared__ float As[8][128];   // transposed A tile
    __shared__ float Bs[8][128];

    int block_row = blockIdx.x * 128;
    int tid = threadIdx.x;
    int tr = tid >> 4;          // 0..15
    int tc = tid & 15;          // 0..15

    // A loading: each thread one float4. 128 rows x 8 cols = 1024 floats = 256 f4.
    int aRow = tid >> 1;            // 0..127
    int aCol = (tid & 1) * 4;       // 0 or 4
    // B loading: 8 rows x 128 cols = 1024 floats = 256 f4.
    int bRow = tid >> 5;            // 0..7
    int bCol = (tid & 31) * 4;      // 0..124

    float acc[8][8];
#pragma unroll
    for (int i = 0; i < 8; i++)
#pragma unroll
        for (int j = 0; j < 8; j++) acc[i][j] = 0.0f;

    for (int k0 = 0; k0 < K; k0 += 8) {
        float4 a4 = make_float4(0.f, 0.f, 0.f, 0.f);
        int gr = block_row + aRow;
        if (gr < M) a4 = *(const float4*)(A + (size_t)gr * K + k0 + aCol);
        As[aCol + 0][aRow] = a4.x;
        As[aCol + 1][aRow] = a4.y;
        As[aCol + 2][aRow] = a4.z;
        As[aCol + 3][aRow] = a4.w;

        float4 b4 = *(const float4*)(B + (size_t)(k0 + bRow) * N + bCol);
        *(float4*)&Bs[bRow][bCol] = b4;

        __syncthreads();

        float regA[8], regB[8];
#pragma unroll
        for (int k = 0; k < 8; k++) {
#pragma unroll
            for (int i = 0; i < 8; i++) regA[i] = As[k][tr * 8 + i];
#pragma unroll
            for (int j = 0; j < 8; j++) regB[j] = Bs[k][tc * 8 + j];
#pragma unroll
            for (int i = 0; i < 8; i++)
#pragma unroll
                for (int j = 0; j < 8; j++) acc[i][j] += regA[i] * regB[j];
        }
        __syncthreads();
    }

#pragma unroll
    for (int i = 0; i < 8; i++) {
        int r = block_row + tr * 8 + i;
        if (r < M) {
#pragma unroll
            for (int j = 0; j < 8; j += 4) {
                float4 v = make_float4(acc[i][j], acc[i][j + 1], acc[i][j + 2], acc[i][j + 3]);
                *(float4*)(C + (size_t)r * N + tc * 8 + j) = v;
            }
        }
    }
}

// agg[dst[e]] += inv_s[src[e]] * feat[src[e]]  -- one warp per edge, float4 per lane.
__global__ __launch_bounds__(256) void spmm_scatter(const float* __restrict__ feat,
                                                    const int* __restrict__ src,
                                                    const int* __restrict__ dst,
                                                    const float* __restrict__ invs,
                                                    float* agg, int nE) {
    int e = blockIdx.x * 8 + (threadIdx.x >> 5);
    if (e >= nE) return;
    int lane = threadIdx.x & 31;
    int s = src[e];
    int d = dst[e];
    float w = invs[s];
    float4 v = *(const float4*)(feat + (size_t)s * FD + lane * 4);
    float* o = agg + (size_t)d * FD + lane * 4;
    atomicAdd(o + 0, w * v.x);
    atomicAdd(o + 1, w * v.y);
    atomicAdd(o + 2, w * v.z);
    atomicAdd(o + 3, w * v.w);
}

// out = aggA*invdA[row] + bA[col] + aggB*invdB[row] + bB[col], optional leaky relu
__global__ void epi2_kernel(float* __restrict__ out,
                            const float* __restrict__ aggA, const float* __restrict__ invdA,
                            const float* __restrict__ bA,
                            const float* __restrict__ aggB, const float* __restrict__ invdB,
                            const float* __restrict__ bB,
                            int rows, int relu) {
    int i = blockIdx.x * blockDim.x + threadIdx.x;
    int total = rows * FD;
    if (i >= total) return;
    int r = i >> 7;
    int c = i & 127;
    float v = aggA[i] * invdA[r] + bA[c] + aggB[i] * invdB[r] + bB[c];
    if (relu) v = v > 0.f ? v : 0.01f * v;
    out[i] = v;
}

__global__ void epi1_kernel(float* __restrict__ out,
                            const float* __restrict__ agg, const float* __restrict__ invd,
                            const float* __restrict__ b,
                            int rows, int relu) {
    int i = blockIdx.x * blockDim.x + threadIdx.x;
    int total = rows * FD;
    if (i >= total) return;
    int r = i >> 7;
    int c = i & 127;
    float v = agg[i] * invd[r] + b[c];
    if (relu) v = v > 0.f ? v : 0.01f * v;
    out[i] = v;
}

// ---------------------------------------------------------------------------
// Host launch
// ---------------------------------------------------------------------------
extern "C" void kernel_launch(void* const* d_in, const int* in_sizes, int n_in,
                              void* d_out, int out_size) {
    const float* x_chem = (const float*)d_in[0];
    const float* x_gene = (const float*)d_in[1];
    const int* src_cc = (const int*)d_in[2];
    const int* dst_cc = (const int*)d_in[3];
    const int* src_cg = (const int*)d_in[4];
    const int* dst_cg = (const int*)d_in[5];
    const int* src_gc = (const int*)d_in[6];
    const int* dst_gc = (const int*)d_in[7];

    // Weight/bias ordering: detect interleaved (W,b,W,b,...) vs grouped (W*6, b*6)
    const float *W1_cc, *W1_cg, *W1_gc, *W2_cc, *W2_cg, *W2_gc;
    const float *b1_cc, *b1_cg, *b1_gc, *b2_cc, *b2_cg, *b2_gc;
    if (in_sizes[9] == FD) {  // interleaved: W1_cc,b1_cc,W1_cg,b1_cg,...
        W1_cc = (const float*)d_in[8];  b1_cc = (const float*)d_in[9];
        W1_cg = (const float*)d_in[10]; b1_cg = (const float*)d_in[11];
        W1_gc = (const float*)d_in[12]; b1_gc = (const float*)d_in[13];
        W2_cc = (const float*)d_in[14]; b2_cc = (const float*)d_in[15];
        W2_cg = (const float*)d_in[16]; b2_cg = (const float*)d_in[17];
        W2_gc = (const float*)d_in[18]; b2_gc = (const float*)d_in[19];
    } else {                  // grouped: all W then all b
        W1_cc = (const float*)d_in[8];
        W1_cg = (const float*)d_in[9];
        W1_gc = (const float*)d_in[10];
        W2_cc = (const float*)d_in[11];
        W2_cg = (const float*)d_in[12];
        W2_gc = (const float*)d_in[13];
        b1_cc = (const float*)d_in[14];
        b1_cg = (const float*)d_in[15];
        b1_gc = (const float*)d_in[16];
        b2_cc = (const float*)d_in[17];
        b2_cg = (const float*)d_in[18];
        b2_gc = (const float*)d_in[19];
    }

    int Nc = in_sizes[0] / FD;
    int Ng = in_sizes[1] / FD;
    int nEcc = in_sizes[2];
    int nEcg = in_sizes[4];
    int nEgc = in_sizes[6];

    float* scratch = nullptr;
    float* deg = nullptr;
    cudaGetSymbolAddress((void**)&scratch, g_scratch);
    cudaGetSymbolAddress((void**)&deg, g_deg);

    float* Ycc = scratch + OFF_YCC;
    float* Ycg = scratch + OFF_YCG;
    float* Ygc = scratch + OFF_YGC;
    float* aggCC = scratch + OFF_AGGCC;
    float* aggGC = scratch + OFF_AGGGC;
    float* aggCG = scratch + OFF_AGGCG;
    float* h1c = scratch + OFF_H1C;
    float* h1g = scratch + OFF_H1G;

    float* invs_cc = deg + DOFF_INVS_CC;
    float* invd_cc = deg + DOFF_INVD_CC;
    float* invs_cg = deg + DOFF_INVS_CG;
    float* invd_cg = deg + DOFF_INVD_CG;
    float* invs_gc = deg + DOFF_INVS_GC;
    float* invd_gc = deg + DOFF_INVD_GC;

    float* out = (float*)d_out;

    // ---- degrees ----
    cudaMemsetAsync(deg, 0, DEG_TOTAL * sizeof(float), 0);
    deg_kernel<<<(nEcc + 255) / 256, 256>>>(src_cc, dst_cc, invs_cc, invd_cc, nEcc);
    deg_kernel<<<(nEcg + 255) / 256, 256>>>(src_cg, dst_cg, invs_cg, invd_cg, nEcg);
    deg_kernel<<<(nEgc + 255) / 256, 256>>>(src_gc, dst_gc, invs_gc, invd_gc, nEgc);
    rsqrt_kernel<<<(DEG_TOTAL + 255) / 256, 256>>>(deg, DEG_TOTAL);

    // ---- layer 1 GEMMs ----
    int gBlkC = (Nc + 127) / 128;
    int gBlkG = (Ng + 127) / 128;
    sgemm128<<<gBlkC, 256>>>(x_chem, W1_cc, Ycc, Nc);
    sgemm128<<<gBlkC, 256>>>(x_chem, W1_cg, Ycg, Nc);
    sgemm128<<<gBlkG, 256>>>(x_gene, W1_gc, Ygc, Ng);

    // ---- layer 1 SpMM ----
    cudaMemsetAsync(aggCC, 0,
                    ((size_t)2 * NC_MAX * FD + (size_t)NG_MAX * FD) * sizeof(float), 0);
    spmm_scatter<<<(nEcc + 7) / 8, 256>>>(Ycc, src_cc, dst_cc, invs_cc, aggCC, nEcc);
    spmm_scatter<<<(nEgc + 7) / 8, 256>>>(Ygc, src_gc, dst_gc, invs_gc, aggGC, nEgc);
    spmm_scatter<<<(nEcg + 7) / 8, 256>>>(Ycg, src_cg, dst_cg, invs_cg, aggCG, nEcg);

    // ---- layer 1 epilogue (bias + sum relations + leaky relu) ----
    epi2_kernel<<<(Nc * FD + 255) / 256, 256>>>(h1c, aggCC, invd_cc, b1_cc,
                                                aggGC, invd_gc, b1_gc, Nc, 1);
    epi1_kernel<<<(Ng * FD + 255) / 256, 256>>>(h1g, aggCG, invd_cg, b1_cg, Ng, 1);

    // ---- layer 2 GEMMs (reuse Ycc/Ygc buffers) ----
    sgemm128<<<gBlkC, 256>>>(h1c, W2_cc, Ycc, Nc);
    sgemm128<<<gBlkG, 256>>>(h1g, W2_gc, Ygc, Ng);

    // ---- layer 2 SpMM ----
    cudaMemsetAsync(aggCC, 0, (size_t)2 * NC_MAX * FD * sizeof(float), 0);
    spmm_scatter<<<(nEcc + 7) / 8, 256>>>(Ycc, src_cc, dst_cc, invs_cc, aggCC, nEcc);
    spmm_scatter<<<(nEgc + 7) / 8, 256>>>(Ygc, src_gc, dst_gc, invs_gc, aggGC, nEgc);

    // ---- final epilogue (no relu) ----
    epi2_kernel<<<(Nc * FD + 255) / 256, 256>>>(out, aggCC, invd_cc, b2_cc,
                                                aggGC, invd_gc, b2_gc, Nc, 0);
}

// round 2
// speedup vs baseline: 2.0713x; 2.0713x over previous
#include <cuda_runtime.h>
#include <cstdint>

// ---------------------------------------------------------------------------
// Problem constants (fixed by the dataset)
// ---------------------------------------------------------------------------
#define NC_MAX 50000
#define NG_MAX 30000
#define FD 128
#define ECC_MAX 500000
#define ECG_MAX 400000
#define EGC_MAX 400000

// Float scratch: Ycc, Ycg (chem-rows), Ygc (gene-rows), h1c, h1g
#define OFF_YCC ((size_t)0)
#define OFF_YCG ((size_t)NC_MAX * FD)
#define OFF_YGC ((size_t)2 * NC_MAX * FD)
#define OFF_H1C (OFF_YGC + (size_t)NG_MAX * FD)
#define OFF_H1G (OFF_H1C + (size_t)NC_MAX * FD)
#define SCRATCH_FLOATS (OFF_H1G + (size_t)NG_MAX * FD)

__device__ float g_scratch[SCRATCH_FLOATS];

// Degree arrays (raw counts, then rsqrt'd in place)
#define DOFF_INVS_CC 0
#define DOFF_INVD_CC (DOFF_INVS_CC + NC_MAX)
#define DOFF_INVS_CG (DOFF_INVD_CC + NC_MAX)
#define DOFF_INVD_CG (DOFF_INVS_CG + NC_MAX)
#define DOFF_INVS_GC (DOFF_INVD_CG + NG_MAX)
#define DOFF_INVD_GC (DOFF_INVS_GC + NG_MAX)
#define DEG_TOTAL    (DOFF_INVD_GC + NC_MAX)

__device__ float g_deg[DEG_TOTAL];

// Int scratch: CSR rowptr/cursor/col arrays
#define IOFF_RP_CC  0
#define IOFF_CUR_CC (IOFF_RP_CC + NC_MAX + 1)
#define IOFF_RP_GC  (IOFF_CUR_CC + NC_MAX)
#define IOFF_CUR_GC (IOFF_RP_GC + NC_MAX + 1)
#define IOFF_RP_CG  (IOFF_CUR_GC + NC_MAX)
#define IOFF_CUR_CG (IOFF_RP_CG + NG_MAX + 1)
#define IOFF_COL_CC (IOFF_CUR_CG + NG_MAX)
#define IOFF_COL_GC (IOFF_COL_CC + ECC_MAX)
#define IOFF_COL_CG (IOFF_COL_GC + EGC_MAX)
#define INT_TOTAL   (IOFF_COL_CG + ECG_MAX)

__device__ int g_int[INT_TOTAL];

// ---------------------------------------------------------------------------
// Degree histogram (float) for both endpoints of a relation
// ---------------------------------------------------------------------------
__global__ void deg_kernel(const int* __restrict__ src, const int* __restrict__ dst,
                           float* degS, float* degD, int nE) {
    int i = blockIdx.x * blockDim.x + threadIdx.x;
    if (i < nE) {
        atomicAdd(&degS[src[i]], 1.0f);
        atomicAdd(&degD[dst[i]], 1.0f);
    }
}

__global__ void rsqrt_kernel(float* d, int n) {
    int i = blockIdx.x * blockDim.x + threadIdx.x;
    if (i < n) d[i] = rsqrtf(fmaxf(d[i], 1.0f));
}

// ---------------------------------------------------------------------------
// 3-way exclusive scan: one block per relation, counts read as float.
// Produces rowptr[n+1] and initializes cursor[n] = rowptr[n].
// ---------------------------------------------------------------------------
__global__ __launch_bounds__(1024) void scan3_kernel(
    const float* d0, int n0, int* rp0, int* cur0,
    const float* d1, int n1, int* rp1, int* cur1,
    const float* d2, int n2, int* rp2, int* cur2) {
    const float* cnt; int n; int* rp; int* cur;
    if (blockIdx.x == 0) { cnt = d0; n = n0; rp = rp0; cur = cur0; }
    else if (blockIdx.x == 1) { cnt = d1; n = n1; rp = rp1; cur = cur1; }
    else { cnt = d2; n = n2; rp = rp2; cur = cur2; }

    __shared__ int warp_sums[32];
    __shared__ int s_carry;
    int tid = threadIdx.x, lane = tid & 31, wid = tid >> 5;
    if (tid == 0) s_carry = 0;
    __syncthreads();

    for (int base = 0; base < n; base += 1024) {
        int i = base + tid;
        int v = (i < n) ? (int)cnt[i] : 0;
        // warp inclusive scan
        int x = v;
#pragma unroll
        for (int off = 1; off < 32; off <<= 1) {
            int y = __shfl_up_sync(0xffffffffu, x, off);
            if (lane >= off) x += y;
        }
        if (lane == 31) warp_sums[wid] = x;
        __syncthreads();
        if (wid == 0) {
            int w = warp_sums[lane];
#pragma unroll
            for (int off = 1; off < 32; off <<= 1) {
                int y = __shfl_up_sync(0xffffffffu, w, off);
                if (lane >= off) w += y;
            }
            warp_sums[lane] = w;
        }
        __syncthreads();
        int warp_off = wid ? warp_sums[wid - 1] : 0;
        int incl = s_carry + warp_off + x;
        if (i < n) {
            rp[i] = incl - v;
            cur[i] = incl - v;
        }
        __syncthreads();
        if (tid == 0) s_carry += warp_sums[31];
        __syncthreads();
    }
    if (threadIdx.x == 0) rp[n] = s_carry;
}

// CSR fill: col[pos] = src, pos taken from per-row atomic cursor
__global__ void fill_kernel(const int* __restrict__ src, const int* __restrict__ dst,
                            int* cur, int* col, int nE) {
    int e = blockIdx.x * blockDim.x + threadIdx.x;
    if (e < nE) {
        int p = atomicAdd(&cur[dst[e]], 1);
        col[p] = src[e];
    }
}

// ---------------------------------------------------------------------------
// C[M,128] = (A[M,128] @ B[128,128]) * rowscale[r]
// 128x128 block tile, 256 threads, 8x8 micro-tile, reg-prefetch pipeline.
// ---------------------------------------------------------------------------
__global__ __launch_bounds__(256) void sgemm128(const float* __restrict__ A,
                                                const float* __restrict__ B,
                                                const float* __restrict__ rowscale,
                                                float* __restrict__ C, int M) {
    const int K = 128, N = 128;
    __shared__ float As[8][128];
    __shared__ float Bs[8][128];

    int block_row = blockIdx.x * 128;
    int tid = threadIdx.x;
    int tr = tid >> 4;
    int tc = tid & 15;

    int aRow = tid >> 1;
    int aCol = (tid & 1) * 4;
    int bRow = tid >> 5;
    int bCol = (tid & 31) * 4;

    float acc[8][8];
#pragma unroll
    for (int i = 0; i < 8; i++)
#pragma unroll
        for (int j = 0; j < 8; j++) acc[i][j] = 0.0f;

    int gr = block_row + aRow;
    bool aValid = (gr < M);
    const float* aPtr = A + (size_t)(aValid ? gr : 0) * K + aCol;
    const float* bPtr = B + (size_t)bRow * N + bCol;

    // preload tile 0
    float4 a4 = make_float4(0.f, 0.f, 0.f, 0.f);
    if (aValid) a4 = *(const float4*)(aPtr);
    float4 b4 = *(const float4*)(bPtr);

    for (int k0 = 0; k0 < K; k0 += 8) {
        As[aCol + 0][aRow] = a4.x;
        As[aCol + 1][aRow] = a4.y;
        As[aCol + 2][aRow] = a4.z;
        As[aCol + 3][aRow] = a4.w;
        *(float4*)&Bs[bRow][bCol] = b4;
        __syncthreads();

        // prefetch next tile while computing
        if (k0 + 8 < K) {
            if (aValid) a4 = *(const float4*)(aPtr + k0 + 8);
            b4 = *(const float4*)(bPtr + (size_t)(k0 + 8) * N);
        }

        float regA[8], regB[8];
#pragma unroll
        for (int k = 0; k < 8; k++) {
#pragma unroll
            for (int i = 0; i < 8; i++) regA[i] = As[k][tr * 8 + i];
#pragma unroll
            for (int j = 0; j < 8; j++) regB[j] = Bs[k][tc * 8 + j];
#pragma unroll
            for (int i = 0; i < 8; i++)
#pragma unroll
                for (int j = 0; j < 8; j++) acc[i][j] += regA[i] * regB[j];
        }
        __syncthreads();
    }

#pragma unroll
    for (int i = 0; i < 8; i++) {
        int r = block_row + tr * 8 + i;
        if (r < M) {
            float s = rowscale[r];
#pragma unroll
            for (int j = 0; j < 8; j += 4) {
                float4 v = make_float4(acc[i][j] * s, acc[i][j + 1] * s,
                                       acc[i][j + 2] * s, acc[i][j + 3] * s);
                *(float4*)(C + (size_t)r * N + tc * 8 + j) = v;
            }
        }
    }
}

// ---------------------------------------------------------------------------
// Fused gather: out[r] = act( (sum_{e in A-row r} featA[colA[e]]) * invdA[r] + bA
//                           + (sum_{e in B-row r} featB[colB[e]]) * invdB[r] + bB )
// One warp per row, float4 per lane.
// ---------------------------------------------------------------------------
__global__ __launch_bounds__(256) void gather2_kernel(
    const int* __restrict__ rpA, const int* __restrict__ colA,
    const float* __restrict__ featA, const float* __restrict__ invdA,
    const float* __restrict__ bA,
    const int* __restrict__ rpB, const int* __restrict__ colB,
    const float* __restrict__ featB, const float* __restrict__ invdB,
    const float* __restrict__ bB,
    float* __restrict__ out, int rows, int relu) {
    int r = blockIdx.x * 8 + (threadIdx.x >> 5);
    if (r >= rows) return;
    int lane = threadIdx.x & 31;
    int lo = lane * 4;

    float4 res;
    {
        float4 acc = make_float4(0.f, 0.f, 0.f, 0.f);
        int j = rpA[r], e = rpA[r + 1];
        for (; j + 1 < e; j += 2) {
            int s0 = colA[j], s1 = colA[j + 1];
            float4 v0 = *(const float4*)(featA + (size_t)s0 * FD + lo);
            float4 v1 = *(const float4*)(featA + (size_t)s1 * FD + lo);
            acc.x += v0.x + v1.x; acc.y += v0.y + v1.y;
            acc.z += v0.z + v1.z; acc.w += v0.w + v1.w;
        }
        if (j < e) {
            int s0 = colA[j];
            float4 v0 = *(const float4*)(featA + (size_t)s0 * FD + lo);
            acc.x += v0.x; acc.y += v0.y; acc.z += v0.z; acc.w += v0.w;
        }
        float w = invdA[r];
        res = make_float4(acc.x * w, acc.y * w, acc.z * w, acc.w * w);
    }
    {
        float4 acc = make_float4(0.f, 0.f, 0.f, 0.f);
        int j = rpB[r], e = rpB[r + 1];
        for (; j + 1 < e; j += 2) {
            int s0 = colB[j], s1 = colB[j + 1];
            float4 v0 = *(const float4*)(featB + (size_t)s0 * FD + lo);
            float4 v1 = *(const float4*)(featB + (size_t)s1 * FD + lo);
            acc.x += v0.x + v1.x; acc.y += v0.y + v1.y;
            acc.z += v0.z + v1.z; acc.w += v0.w + v1.w;
        }
        if (j < e) {
            int s0 = colB[j];
            float4 v0 = *(const float4*)(featB + (size_t)s0 * FD + lo);
            acc.x += v0.x; acc.y += v0.y; acc.z += v0.z; acc.w += v0.w;
        }
        float w = invdB[r];
        res.x += acc.x * w; res.y += acc.y * w;
        res.z += acc.z * w; res.w += acc.w * w;
    }
    float4 biasA = *(const float4*)(bA + lo);
    float4 biasB = *(const float4*)(bB + lo);
    res.x += biasA.x + biasB.x;
    res.y += biasA.y + biasB.y;
    res.z += biasA.z + biasB.z;
    res.w += biasA.w + biasB.w;
    if (relu) {
        res.x = res.x > 0.f ? res.x : 0.01f * res.x;
        res.y = res.y > 0.f ? res.y : 0.01f * res.y;
        res.z = res.z > 0.f ? res.z : 0.01f * res.z;
        res.w = res.w > 0.f ? res.w : 0.01f * res.w;
    }
    *(float4*)(out + (size_t)r * FD + lo) = res;
}

__global__ __launch_bounds__(256) void gather1_kernel(
    const int* __restrict__ rp, const int* __restrict__ col,
    const float* __restrict__ feat, const float* __restrict__ invd,
    const float* __restrict__ b,
    float* __restrict__ out, int rows, int relu) {
    int r = blockIdx.x * 8 + (threadIdx.x >> 5);
    if (r >= rows) return;
    int lane = threadIdx.x & 31;
    int lo = lane * 4;

    float4 acc = make_float4(0.f, 0.f, 0.f, 0.f);
    int j = rp[r], e = rp[r + 1];
    for (; j + 1 < e; j += 2) {
        int s0 = col[j], s1 = col[j + 1];
        float4 v0 = *(const float4*)(feat + (size_t)s0 * FD + lo);
        float4 v1 = *(const float4*)(feat + (size_t)s1 * FD + lo);
        acc.x += v0.x + v1.x; acc.y += v0.y + v1.y;
        acc.z += v0.z + v1.z; acc.w += v0.w + v1.w;
    }
    if (j < e) {
        int s0 = col[j];
        float4 v0 = *(const float4*)(feat + (size_t)s0 * FD + lo);
        acc.x += v0.x; acc.y += v0.y; acc.z += v0.z; acc.w += v0.w;
    }
    float w = invd[r];
    float4 bb = *(const float4*)(b + lo);
    float4 res = make_float4(acc.x * w + bb.x, acc.y * w + bb.y,
                             acc.z * w + bb.z, acc.w * w + bb.w);
    if (relu) {
        res.x = res.x > 0.f ? res.x : 0.01f * res.x;
        res.y = res.y > 0.f ? res.y : 0.01f * res.y;
        res.z = res.z > 0.f ? res.z : 0.01f * res.z;
        res.w = res.w > 0.f ? res.w : 0.01f * res.w;
    }
    *(float4*)(out + (size_t)r * FD + lo) = res;
}

// ---------------------------------------------------------------------------
// Host launch
// ---------------------------------------------------------------------------
extern "C" void kernel_launch(void* const* d_in, const int* in_sizes, int n_in,
                              void* d_out, int out_size) {
    const float* x_chem = (const float*)d_in[0];
    const float* x_gene = (const float*)d_in[1];
    const int* src_cc = (const int*)d_in[2];
    const int* dst_cc = (const int*)d_in[3];
    const int* src_cg = (const int*)d_in[4];
    const int* dst_cg = (const int*)d_in[5];
    const int* src_gc = (const int*)d_in[6];
    const int* dst_gc = (const int*)d_in[7];

    const float *W1_cc, *W1_cg, *W1_gc, *W2_cc, *W2_cg, *W2_gc;
    const float *b1_cc, *b1_cg, *b1_gc, *b2_cc, *b2_cg, *b2_gc;
    if (in_sizes[9] == FD) {  // interleaved
        W1_cc = (const float*)d_in[8];  b1_cc = (const float*)d_in[9];
        W1_cg = (const float*)d_in[10]; b1_cg = (const float*)d_in[11];
        W1_gc = (const float*)d_in[12]; b1_gc = (const float*)d_in[13];
        W2_cc = (const float*)d_in[14]; b2_cc = (const float*)d_in[15];
        W2_cg = (const float*)d_in[16]; b2_cg = (const float*)d_in[17];
        W2_gc = (const float*)d_in[18]; b2_gc = (const float*)d_in[19];
    } else {                  // grouped
        W1_cc = (const float*)d_in[8];
        W1_cg = (const float*)d_in[9];
        W1_gc = (const float*)d_in[10];
        W2_cc = (const float*)d_in[11];
        W2_cg = (const float*)d_in[12];
        W2_gc = (const float*)d_in[13];
        b1_cc = (const float*)d_in[14];
        b1_cg = (const float*)d_in[15];
        b1_gc = (const float*)d_in[16];
        b2_cc = (const float*)d_in[17];
        b2_cg = (const float*)d_in[18];
        b2_gc = (const float*)d_in[19];
    }

    int Nc = in_sizes[0] / FD;
    int Ng = in_sizes[1] / FD;
    int nEcc = in_sizes[2];
    int nEcg = in_sizes[4];
    int nEgc = in_sizes[6];

    float* scratch = nullptr;
    float* deg = nullptr;
    int* ints = nullptr;
    cudaGetSymbolAddress((void**)&scratch, g_scratch);
    cudaGetSymbolAddress((void**)&deg, g_deg);
    cudaGetSymbolAddress((void**)&ints, g_int);

    float* Ycc = scratch + OFF_YCC;
    float* Ycg = scratch + OFF_YCG;
    float* Ygc = scratch + OFF_YGC;
    float* h1c = scratch + OFF_H1C;
    float* h1g = scratch + OFF_H1G;

    float* invs_cc = deg + DOFF_INVS_CC;
    float* invd_cc = deg + DOFF_INVD_CC;
    float* invs_cg = deg + DOFF_INVS_CG;
    float* invd_cg = deg + DOFF_INVD_CG;
    float* invs_gc = deg + DOFF_INVS_GC;
    float* invd_gc = deg + DOFF_INVD_GC;

    int* rp_cc = ints + IOFF_RP_CC;
    int* cur_cc = ints + IOFF_CUR_CC;
    int* rp_gc = ints + IOFF_RP_GC;
    int* cur_gc = ints + IOFF_CUR_GC;
    int* rp_cg = ints + IOFF_RP_CG;
    int* cur_cg = ints + IOFF_CUR_CG;
    int* col_cc = ints + IOFF_COL_CC;
    int* col_gc = ints + IOFF_COL_GC;
    int* col_cg = ints + IOFF_COL_CG;

    float* out = (float*)d_out;

    // ---- degrees (counts) ----
    cudaMemsetAsync(deg, 0, DEG_TOTAL * sizeof(float), 0);
    deg_kernel<<<(nEcc + 255) / 256, 256>>>(src_cc, dst_cc, invs_cc, invd_cc, nEcc);
    deg_kernel<<<(nEcg + 255) / 256, 256>>>(src_cg, dst_cg, invs_cg, invd_cg, nEcg);
    deg_kernel<<<(nEgc + 255) / 256, 256>>>(src_gc, dst_gc, invs_gc, invd_gc, nEgc);

    // ---- CSR build: scan in-degree counts (still raw), then fill ----
    scan3_kernel<<<3, 1024>>>(invd_cc, Nc, rp_cc, cur_cc,
                              invd_gc, Nc, rp_gc, cur_gc,
                              invd_cg, Ng, rp_cg, cur_cg);
    rsqrt_kernel<<<(DEG_TOTAL + 255) / 256, 256>>>(deg, DEG_TOTAL);
    fill_kernel<<<(nEcc + 255) / 256, 256>>>(src_cc, dst_cc, cur_cc, col_cc, nEcc);
    fill_kernel<<<(nEgc + 255) / 256, 256>>>(src_gc, dst_gc, cur_gc, col_gc, nEgc);
    fill_kernel<<<(nEcg + 255) / 256, 256>>>(src_cg, dst_cg, cur_cg, col_cg, nEcg);

    // ---- layer 1 GEMMs (inv_s folded into output rows) ----
    int gBlkC = (Nc + 127) / 128;
    int gBlkG = (Ng + 127) / 128;
    sgemm128<<<gBlkC, 256>>>(x_chem, W1_cc, invs_cc, Ycc, Nc);
    sgemm128<<<gBlkC, 256>>>(x_chem, W1_cg, invs_cg, Ycg, Nc);
    sgemm128<<<gBlkG, 256>>>(x_gene, W1_gc, invs_gc, Ygc, Ng);

    // ---- layer 1 fused gather + bias + leaky relu ----
    gather2_kernel<<<(Nc + 7) / 8, 256>>>(rp_cc, col_cc, Ycc, invd_cc, b1_cc,
                                          rp_gc, col_gc, Ygc, invd_gc, b1_gc,
                                          h1c, Nc, 1);
    gather1_kernel<<<(Ng + 7) / 8, 256>>>(rp_cg, col_cg, Ycg, invd_cg, b1_cg,
                                          h1g, Ng, 1);

    // ---- layer 2 GEMMs (reuse Ycc/Ygc) ----
    sgemm128<<<gBlkC, 256>>>(h1c, W2_cc, invs_cc, Ycc, Nc);
    sgemm128<<<gBlkG, 256>>>(h1g, W2_gc, invs_gc, Ygc, Ng);

    // ---- layer 2 fused gather -> output ----
    gather2_kernel<<<(Nc + 7) / 8, 256>>>(rp_cc, col_cc, Ycc, invd_cc, b2_cc,
                                          rp_gc, col_gc, Ygc, invd_gc, b2_gc,
                                          out, Nc, 0);
}

// round 3
// speedup vs baseline: 3.9209x; 1.8929x over previous
#include <cuda_runtime.h>
#include <cstdint>

// ---------------------------------------------------------------------------
// Problem constants (fixed by the dataset)
// ---------------------------------------------------------------------------
#define NC_MAX 50000
#define NG_MAX 30000
#define FD 128
#define ECC_MAX 500000
#define ECG_MAX 400000
#define EGC_MAX 400000

// Float scratch
#define OFF_YCC ((size_t)0)
#define OFF_YCG ((size_t)NC_MAX * FD)
#define OFF_YGC ((size_t)2 * NC_MAX * FD)
#define OFF_H1C (OFF_YGC + (size_t)NG_MAX * FD)
#define OFF_H1G (OFF_H1C + (size_t)NC_MAX * FD)
#define SCRATCH_FLOATS (OFF_H1G + (size_t)NG_MAX * FD)

__device__ float g_scratch[SCRATCH_FLOATS];

// Degree arrays (raw counts, then rsqrt'd in place)
#define DOFF_INVS_CC 0
#define DOFF_INVD_CC (DOFF_INVS_CC + NC_MAX)
#define DOFF_INVS_CG (DOFF_INVD_CC + NC_MAX)
#define DOFF_INVD_CG (DOFF_INVS_CG + NC_MAX)
#define DOFF_INVS_GC (DOFF_INVD_CG + NG_MAX)
#define DOFF_INVD_GC (DOFF_INVS_GC + NG_MAX)
#define DEG_TOTAL    (DOFF_INVD_GC + NC_MAX)

__device__ float g_deg[DEG_TOTAL];

// Int scratch: CSR rowptr/cursor/col arrays + block sums for scan
#define IOFF_RP_CC  0
#define IOFF_CUR_CC (IOFF_RP_CC + NC_MAX + 1)
#define IOFF_RP_GC  (IOFF_CUR_CC + NC_MAX)
#define IOFF_CUR_GC (IOFF_RP_GC + NC_MAX + 1)
#define IOFF_RP_CG  (IOFF_CUR_GC + NC_MAX)
#define IOFF_CUR_CG (IOFF_RP_CG + NG_MAX + 1)
#define IOFF_COL_CC (IOFF_CUR_CG + NG_MAX)
#define IOFF_COL_GC (IOFF_COL_CC + ECC_MAX)
#define IOFF_COL_CG (IOFF_COL_GC + EGC_MAX)
#define IOFF_BSUM   (IOFF_COL_CG + ECG_MAX)
#define INT_TOTAL   (IOFF_BSUM + 128)

__device__ int g_int[INT_TOTAL];

// ---------------------------------------------------------------------------
// Degree histogram
// ---------------------------------------------------------------------------
__global__ void deg_kernel(const int* __restrict__ src, const int* __restrict__ dst,
                           float* degS, float* degD, int nE) {
    int i = blockIdx.x * blockDim.x + threadIdx.x;
    if (i < nE) {
        atomicAdd(&degS[src[i]], 1.0f);
        atomicAdd(&degD[dst[i]], 1.0f);
    }
}

__global__ void rsqrt_kernel(float* d, int n) {
    int i = blockIdx.x * blockDim.x + threadIdx.x;
    if (i < n) d[i] = rsqrtf(fmaxf(d[i], 1.0f));
}

// ---------------------------------------------------------------------------
// Parallel 3-relation exclusive scan, 3 passes. 4096 elems per block.
// ---------------------------------------------------------------------------
#define SCAN_TILE 4096

__global__ __launch_bounds__(256) void scan_pass1(
    const float* c0, int n0, const float* c1, int n1, const float* c2, int n2,
    int nb0, int nb1, int* bsum) {
    int gb = blockIdx.x;
    const float* cnt; int n; int lb;
    if (gb < nb0) { cnt = c0; n = n0; lb = gb; }
    else if (gb < nb0 + nb1) { cnt = c1; n = n1; lb = gb - nb0; }
    else { cnt = c2; n = n2; lb = gb - nb0 - nb1; }

    int base = lb * SCAN_TILE + threadIdx.x * 16;
    int s = 0;
#pragma unroll
    for (int j = 0; j < 16; j++) {
        int i = base + j;
        if (i < n) s += (int)cnt[i];
    }
#pragma unroll
    for (int o = 16; o; o >>= 1) s += __shfl_down_sync(0xffffffffu, s, o);
    __shared__ int ws[8];
    if ((threadIdx.x & 31) == 0) ws[threadIdx.x >> 5] = s;
    __syncthreads();
    if (threadIdx.x == 0) {
        int t = 0;
        for (int w = 0; w < 8; w++) t += ws[w];
        bsum[gb] = t;
    }
}

__global__ void scan_pass2(int* bsum, int nb0, int nb1, int nb2,
                           int* rp0, int n0, int* rp1, int n1, int* rp2, int n2) {
    if (threadIdx.x == 0 && blockIdx.x == 0) {
        int carry = 0;
        for (int i = 0; i < nb0; i++) { int v = bsum[i]; bsum[i] = carry; carry += v; }
        rp0[n0] = carry; carry = 0;
        for (int i = nb0; i < nb0 + nb1; i++) { int v = bsum[i]; bsum[i] = carry; carry += v; }
        rp1[n1] = carry; carry = 0;
        for (int i = nb0 + nb1; i < nb0 + nb1 + nb2; i++) { int v = bsum[i]; bsum[i] = carry; carry += v; }
        rp2[n2] = carry;
    }
}

__global__ __launch_bounds__(256) void scan_pass3(
    const float* c0, int n0, int* rp0, int* cur0,
    const float* c1, int n1, int* rp1, int* cur1,
    const float* c2, int n2, int* rp2, int* cur2,
    int nb0, int nb1, const int* __restrict__ bsum) {
    int gb = blockIdx.x;
    const float* cnt; int n; int lb; int* rp; int* cur;
    if (gb < nb0) { cnt = c0; n = n0; lb = gb; rp = rp0; cur = cur0; }
    else if (gb < nb0 + nb1) { cnt = c1; n = n1; lb = gb - nb0; rp = rp1; cur = cur1; }
    else { cnt = c2; n = n2; lb = gb - nb0 - nb1; rp = rp2; cur = cur2; }

    int base = lb * SCAN_TILE + threadIdx.x * 16;
    int v[16];
    int s = 0;
#pragma unroll
    for (int j = 0; j < 16; j++) {
        int i = base + j;
        v[j] = (i < n) ? (int)cnt[i] : 0;
        s += v[j];
    }
    int lane = threadIdx.x & 31, w = threadIdx.x >> 5;
    int x = s;
#pragma unroll
    for (int o = 1; o < 32; o <<= 1) {
        int y = __shfl_up_sync(0xffffffffu, x, o);
        if (lane >= o) x += y;
    }
    __shared__ int ws[8];
    if (lane == 31) ws[w] = x;
    __syncthreads();
    int woff = 0;
    for (int i = 0; i < w; i++) woff += ws[i];
    int excl = woff + (x - s) + bsum[gb];
#pragma unroll
    for (int j = 0; j < 16; j++) {
        int i = base + j;
        if (i < n) { rp[i] = excl; cur[i] = excl; }
        excl += v[j];
    }
}

// CSR fill
__global__ void fill_kernel(const int* __restrict__ src, const int* __restrict__ dst,
                            int* cur, int* col, int nE) {
    int e = blockIdx.x * blockDim.x + threadIdx.x;
    if (e < nE) {
        int p = atomicAdd(&cur[dst[e]], 1);
        col[p] = src[e];
    }
}

// ---------------------------------------------------------------------------
// TF32 tensor-core GEMM: C[M,128] = (A[M,128] @ B[128,128]) * rowscale[r]
// 128x128 block tile, 256 threads = 8 warps (4m x 2n), warp tile 32x64,
// mma.sync m16n8k8 tf32. K chunked by 32 through smem.
// ---------------------------------------------------------------------------
__device__ __forceinline__ float f2tf32(float x) {
    uint32_t u;
    asm("cvt.rna.tf32.f32 %0, %1;" : "=r"(u) : "f"(x));
    return __uint_as_float(u);
}

#define KC 32

__global__ __launch_bounds__(256) void sgemm_tf32(const float* __restrict__ A,
                                                  const float* __restrict__ B,
                                                  const float* __restrict__ rowscale,
                                                  float* __restrict__ C, int M) {
    __shared__ float As[128][36];   // [m][k], stride 36 -> frag bank = 4r+c (bijective)
    __shared__ float Bs[KC][136];   // [k][n], stride 136 -> frag bank = 8c+r (bijective)

    int tid = threadIdx.x;
    int warp = tid >> 5, lane = tid & 31;
    int wm = (warp >> 1) * 32;   // 0,32,64,96
    int wn = (warp & 1) * 64;    // 0,64
    int g = lane >> 2;           // groupID
    int t = lane & 3;            // threadID in group
    int block_row = blockIdx.x * 128;

    float acc[2][8][4];
#pragma unroll
    for (int i = 0; i < 2; i++)
#pragma unroll
        for (int j = 0; j < 8; j++)
#pragma unroll
            for (int k = 0; k < 4; k++) acc[i][j][k] = 0.0f;

    int ar = tid >> 3;           // 0..31
    int ac = (tid & 7) * 4;      // 0..28
    int br = tid >> 5;           // 0..7
    int bc = (tid & 31) * 4;     // 0..124

    for (int k0 = 0; k0 < 128; k0 += KC) {
        // load A chunk (128 x 32)
#pragma unroll
        for (int i = 0; i < 4; i++) {
            int r = ar + 32 * i;
            int gr = block_row + r;
            float4 v = make_float4(0.f, 0.f, 0.f, 0.f);
            if (gr < M) v = *(const float4*)(A + (size_t)gr * 128 + k0 + ac);
            As[r][ac + 0] = f2tf32(v.x);
            As[r][ac + 1] = f2tf32(v.y);
            As[r][ac + 2] = f2tf32(v.z);
            As[r][ac + 3] = f2tf32(v.w);
        }
        // load B chunk (32 x 128)
#pragma unroll
        for (int i = 0; i < 4; i++) {
            int k = br + 8 * i;
            float4 v = *(const float4*)(B + (size_t)(k0 + k) * 128 + bc);
            Bs[k][bc + 0] = f2tf32(v.x);
            Bs[k][bc + 1] = f2tf32(v.y);
            Bs[k][bc + 2] = f2tf32(v.z);
            Bs[k][bc + 3] = f2tf32(v.w);
        }
        __syncthreads();

#pragma unroll
        for (int kk = 0; kk < KC; kk += 8) {
            uint32_t af[2][4];
#pragma unroll
            for (int ti = 0; ti < 2; ti++) {
                int row = wm + 16 * ti + g;
                int col = kk + t;
                af[ti][0] = __float_as_uint(As[row][col]);
                af[ti][1] = __float_as_uint(As[row + 8][col]);
                af[ti][2] = __float_as_uint(As[row][col + 4]);
                af[ti][3] = __float_as_uint(As[row + 8][col + 4]);
            }
            uint32_t bf[8][2];
#pragma unroll
            for (int u = 0; u < 8; u++) {
                int k = kk + t;
                int n = wn + 8 * u + g;
                bf[u][0] = __float_as_uint(Bs[k][n]);
                bf[u][1] = __float_as_uint(Bs[k + 4][n]);
            }
#pragma unroll
            for (int ti = 0; ti < 2; ti++)
#pragma unroll
                for (int u = 0; u < 8; u++) {
                    asm volatile(
                        "mma.sync.aligned.m16n8k8.row.col.f32.tf32.tf32.f32 "
                        "{%0,%1,%2,%3}, {%4,%5,%6,%7}, {%8,%9}, {%0,%1,%2,%3};\n"
                        : "+f"(acc[ti][u][0]), "+f"(acc[ti][u][1]),
                          "+f"(acc[ti][u][2]), "+f"(acc[ti][u][3])
                        : "r"(af[ti][0]), "r"(af[ti][1]), "r"(af[ti][2]), "r"(af[ti][3]),
                          "r"(bf[u][0]), "r"(bf[u][1]));
                }
        }
        __syncthreads();
    }

    // epilogue: scale rows, write float2 pairs
#pragma unroll
    for (int ti = 0; ti < 2; ti++) {
        int row0 = block_row + wm + 16 * ti + g;
        int row1 = row0 + 8;
        float s0 = (row0 < M) ? rowscale[row0] : 0.f;
        float s1 = (row1 < M) ? rowscale[row1] : 0.f;
#pragma unroll
        for (int u = 0; u < 8; u++) {
            int cb = wn + 8 * u + 2 * t;
            if (row0 < M) {
                float2 v0 = make_float2(acc[ti][u][0] * s0, acc[ti][u][1] * s0);
                *(float2*)(C + (size_t)row0 * 128 + cb) = v0;
            }
            if (row1 < M) {
                float2 v1 = make_float2(acc[ti][u][2] * s1, acc[ti][u][3] * s1);
                *(float2*)(C + (size_t)row1 * 128 + cb) = v1;
            }
        }
    }
}

// ---------------------------------------------------------------------------
// Fused gathers (unchanged from round 2)
// ---------------------------------------------------------------------------
__global__ __launch_bounds__(256) void gather2_kernel(
    const int* __restrict__ rpA, const int* __restrict__ colA,
    const float* __restrict__ featA, const float* __restrict__ invdA,
    const float* __restrict__ bA,
    const int* __restrict__ rpB, const int* __restrict__ colB,
    const float* __restrict__ featB, const float* __restrict__ invdB,
    const float* __restrict__ bB,
    float* __restrict__ out, int rows, int relu) {
    int r = blockIdx.x * 8 + (threadIdx.x >> 5);
    if (r >= rows) return;
    int lane = threadIdx.x & 31;
    int lo = lane * 4;

    float4 res;
    {
        float4 acc = make_float4(0.f, 0.f, 0.f, 0.f);
        int j = rpA[r], e = rpA[r + 1];
        for (; j + 1 < e; j += 2) {
            int s0 = colA[j], s1 = colA[j + 1];
            float4 v0 = *(const float4*)(featA + (size_t)s0 * FD + lo);
            float4 v1 = *(const float4*)(featA + (size_t)s1 * FD + lo);
            acc.x += v0.x + v1.x; acc.y += v0.y + v1.y;
            acc.z += v0.z + v1.z; acc.w += v0.w + v1.w;
        }
        if (j < e) {
            int s0 = colA[j];
            float4 v0 = *(const float4*)(featA + (size_t)s0 * FD + lo);
            acc.x += v0.x; acc.y += v0.y; acc.z += v0.z; acc.w += v0.w;
        }
        float w = invdA[r];
        res = make_float4(acc.x * w, acc.y * w, acc.z * w, acc.w * w);
    }
    {
        float4 acc = make_float4(0.f, 0.f, 0.f, 0.f);
        int j = rpB[r], e = rpB[r + 1];
        for (; j + 1 < e; j += 2) {
            int s0 = colB[j], s1 = colB[j + 1];
            float4 v0 = *(const float4*)(featB + (size_t)s0 * FD + lo);
            float4 v1 = *(const float4*)(featB + (size_t)s1 * FD + lo);
            acc.x += v0.x + v1.x; acc.y += v0.y + v1.y;
            acc.z += v0.z + v1.z; acc.w += v0.w + v1.w;
        }
        if (j < e) {
            int s0 = colB[j];
            float4 v0 = *(const float4*)(featB + (size_t)s0 * FD + lo);
            acc.x += v0.x; acc.y += v0.y; acc.z += v0.z; acc.w += v0.w;
        }
        float w = invdB[r];
        res.x += acc.x * w; res.y += acc.y * w;
        res.z += acc.z * w; res.w += acc.w * w;
    }
    float4 biasA = *(const float4*)(bA + lo);
    float4 biasB = *(const float4*)(bB + lo);
    res.x += biasA.x + biasB.x;
    res.y += biasA.y + biasB.y;
    res.z += biasA.z + biasB.z;
    res.w += biasA.w + biasB.w;
    if (relu) {
        res.x = res.x > 0.f ? res.x : 0.01f * res.x;
        res.y = res.y > 0.f ? res.y : 0.01f * res.y;
        res.z = res.z > 0.f ? res.z : 0.01f * res.z;
        res.w = res.w > 0.f ? res.w : 0.01f * res.w;
    }
    *(float4*)(out + (size_t)r * FD + lo) = res;
}

__global__ __launch_bounds__(256) void gather1_kernel(
    const int* __restrict__ rp, const int* __restrict__ col,
    const float* __restrict__ feat, const float* __restrict__ invd,
    const float* __restrict__ b,
    float* __restrict__ out, int rows, int relu) {
    int r = blockIdx.x * 8 + (threadIdx.x >> 5);
    if (r >= rows) return;
    int lane = threadIdx.x & 31;
    int lo = lane * 4;

    float4 acc = make_float4(0.f, 0.f, 0.f, 0.f);
    int j = rp[r], e = rp[r + 1];
    for (; j + 1 < e; j += 2) {
        int s0 = col[j], s1 = col[j + 1];
        float4 v0 = *(const float4*)(feat + (size_t)s0 * FD + lo);
        float4 v1 = *(const float4*)(feat + (size_t)s1 * FD + lo);
        acc.x += v0.x + v1.x; acc.y += v0.y + v1.y;
        acc.z += v0.z + v1.z; acc.w += v0.w + v1.w;
    }
    if (j < e) {
        int s0 = col[j];
        float4 v0 = *(const float4*)(feat + (size_t)s0 * FD + lo);
        acc.x += v0.x; acc.y += v0.y; acc.z += v0.z; acc.w += v0.w;
    }
    float w = invd[r];
    float4 bb = *(const float4*)(b + lo);
    float4 res = make_float4(acc.x * w + bb.x, acc.y * w + bb.y,
                             acc.z * w + bb.z, acc.w * w + bb.w);
    if (relu) {
        res.x = res.x > 0.f ? res.x : 0.01f * res.x;
        res.y = res.y > 0.f ? res.y : 0.01f * res.y;
        res.z = res.z > 0.f ? res.z : 0.01f * res.z;
        res.w = res.w > 0.f ? res.w : 0.01f * res.w;
    }
    *(float4*)(out + (size_t)r * FD + lo) = res;
}

// ---------------------------------------------------------------------------
// Host launch
// ---------------------------------------------------------------------------
extern "C" void kernel_launch(void* const* d_in, const int* in_sizes, int n_in,
                              void* d_out, int out_size) {
    const float* x_chem = (const float*)d_in[0];
    const float* x_gene = (const float*)d_in[1];
    const int* src_cc = (const int*)d_in[2];
    const int* dst_cc = (const int*)d_in[3];
    const int* src_cg = (const int*)d_in[4];
    const int* dst_cg = (const int*)d_in[5];
    const int* src_gc = (const int*)d_in[6];
    const int* dst_gc = (const int*)d_in[7];

    const float *W1_cc, *W1_cg, *W1_gc, *W2_cc, *W2_cg, *W2_gc;
    const float *b1_cc, *b1_cg, *b1_gc, *b2_cc, *b2_cg, *b2_gc;
    if (in_sizes[9] == FD) {  // interleaved
        W1_cc = (const float*)d_in[8];  b1_cc = (const float*)d_in[9];
        W1_cg = (const float*)d_in[10]; b1_cg = (const float*)d_in[11];
        W1_gc = (const float*)d_in[12]; b1_gc = (const float*)d_in[13];
        W2_cc = (const float*)d_in[14]; b2_cc = (const float*)d_in[15];
        W2_cg = (const float*)d_in[16]; b2_cg = (const float*)d_in[17];
        W2_gc = (const float*)d_in[18]; b2_gc = (const float*)d_in[19];
    } else {                  // grouped
        W1_cc = (const float*)d_in[8];
        W1_cg = (const float*)d_in[9];
        W1_gc = (const float*)d_in[10];
        W2_cc = (const float*)d_in[11];
        W2_cg = (const float*)d_in[12];
        W2_gc = (const float*)d_in[13];
        b1_cc = (const float*)d_in[14];
        b1_cg = (const float*)d_in[15];
        b1_gc = (const float*)d_in[16];
        b2_cc = (const float*)d_in[17];
        b2_cg = (const float*)d_in[18];
        b2_gc = (const float*)d_in[19];
    }

    int Nc = in_sizes[0] / FD;
    int Ng = in_sizes[1] / FD;
    int nEcc = in_sizes[2];
    int nEcg = in_sizes[4];
    int nEgc = in_sizes[6];

    float* scratch = nullptr;
    float* deg = nullptr;
    int* ints = nullptr;
    cudaGetSymbolAddress((void**)&scratch, g_scratch);
    cudaGetSymbolAddress((void**)&deg, g_deg);
    cudaGetSymbolAddress((void**)&ints, g_int);

    float* Ycc = scratch + OFF_YCC;
    float* Ycg = scratch + OFF_YCG;
    float* Ygc = scratch + OFF_YGC;
    float* h1c = scratch + OFF_H1C;
    float* h1g = scratch + OFF_H1G;

    float* invs_cc = deg + DOFF_INVS_CC;
    float* invd_cc = deg + DOFF_INVD_CC;
    float* invs_cg = deg + DOFF_INVS_CG;
    float* invd_cg = deg + DOFF_INVD_CG;
    float* invs_gc = deg + DOFF_INVS_GC;
    float* invd_gc = deg + DOFF_INVD_GC;

    int* rp_cc = ints + IOFF_RP_CC;
    int* cur_cc = ints + IOFF_CUR_CC;
    int* rp_gc = ints + IOFF_RP_GC;
    int* cur_gc = ints + IOFF_CUR_GC;
    int* rp_cg = ints + IOFF_RP_CG;
    int* cur_cg = ints + IOFF_CUR_CG;
    int* col_cc = ints + IOFF_COL_CC;
    int* col_gc = ints + IOFF_COL_GC;
    int* col_cg = ints + IOFF_COL_CG;
    int* bsum = ints + IOFF_BSUM;

    float* out = (float*)d_out;

    // ---- degrees (counts) ----
    cudaMemsetAsync(deg, 0, DEG_TOTAL * sizeof(float), 0);
    deg_kernel<<<(nEcc + 255) / 256, 256>>>(src_cc, dst_cc, invs_cc, invd_cc, nEcc);
    deg_kernel<<<(nEcg + 255) / 256, 256>>>(src_cg, dst_cg, invs_cg, invd_cg, nEcg);
    deg_kernel<<<(nEgc + 255) / 256, 256>>>(src_gc, dst_gc, invs_gc, invd_gc, nEgc);

    // ---- parallel CSR scan over in-degree counts ----
    int nb0 = (Nc + SCAN_TILE - 1) / SCAN_TILE;
    int nb1 = (Nc + SCAN_TILE - 1) / SCAN_TILE;
    int nb2 = (Ng + SCAN_TILE - 1) / SCAN_TILE;
    int nbT = nb0 + nb1 + nb2;
    scan_pass1<<<nbT, 256>>>(invd_cc, Nc, invd_gc, Nc, invd_cg, Ng, nb0, nb1, bsum);
    scan_pass2<<<1, 32>>>(bsum, nb0, nb1, nb2, rp_cc, Nc, rp_gc, Nc, rp_cg, Ng);
    scan_pass3<<<nbT, 256>>>(invd_cc, Nc, rp_cc, cur_cc,
                             invd_gc, Nc, rp_gc, cur_gc,
                             invd_cg, Ng, rp_cg, cur_cg,
                             nb0, nb1, bsum);
    rsqrt_kernel<<<(DEG_TOTAL + 255) / 256, 256>>>(deg, DEG_TOTAL);
    fill_kernel<<<(nEcc + 255) / 256, 256>>>(src_cc, dst_cc, cur_cc, col_cc, nEcc);
    fill_kernel<<<(nEgc + 255) / 256, 256>>>(src_gc, dst_gc, cur_gc, col_gc, nEgc);
    fill_kernel<<<(nEcg + 255) / 256, 256>>>(src_cg, dst_cg, cur_cg, col_cg, nEcg);

    // ---- layer 1 GEMMs (tf32 tensor cores, inv_s folded) ----
    int gBlkC = (Nc + 127) / 128;
    int gBlkG = (Ng + 127) / 128;
    sgemm_tf32<<<gBlkC, 256>>>(x_chem, W1_cc, invs_cc, Ycc, Nc);
    sgemm_tf32<<<gBlkC, 256>>>(x_chem, W1_cg, invs_cg, Ycg, Nc);
    sgemm_tf32<<<gBlkG, 256>>>(x_gene, W1_gc, invs_gc, Ygc, Ng);

    // ---- layer 1 fused gather + bias + leaky relu ----
    gather2_kernel<<<(Nc + 7) / 8, 256>>>(rp_cc, col_cc, Ycc, invd_cc, b1_cc,
                                          rp_gc, col_gc, Ygc, invd_gc, b1_gc,
                                          h1c, Nc, 1);
    gather1_kernel<<<(Ng + 7) / 8, 256>>>(rp_cg, col_cg, Ycg, invd_cg, b1_cg,
                                          h1g, Ng, 1);

    // ---- layer 2 GEMMs ----
    sgemm_tf32<<<gBlkC, 256>>>(h1c, W2_cc, invs_cc, Ycc, Nc);
    sgemm_tf32<<<gBlkG, 256>>>(h1g, W2_gc, invs_gc, Ygc, Ng);

    // ---- layer 2 fused gather -> output ----
    gather2_kernel<<<(Nc + 7) / 8, 256>>>(rp_cc, col_cc, Ycc, invd_cc, b2_cc,
                                          rp_gc, col_gc, Ygc, invd_gc, b2_gc,
                                          out, Nc, 0);
}

// round 4
// speedup vs baseline: 4.1894x; 1.0685x over previous
#include <cuda_runtime.h>
#include <cstdint>

// ---------------------------------------------------------------------------
// Problem constants
// ---------------------------------------------------------------------------
#define NC_MAX 50000
#define NG_MAX 30000
#define FD 128
#define ECC_MAX 500000
#define ECG_MAX 400000
#define EGC_MAX 400000

// Float scratch
#define OFF_YCC ((size_t)0)
#define OFF_YCG ((size_t)NC_MAX * FD)
#define OFF_YGC ((size_t)2 * NC_MAX * FD)
#define OFF_H1C (OFF_YGC + (size_t)NG_MAX * FD)
#define OFF_H1G (OFF_H1C + (size_t)NC_MAX * FD)
#define SCRATCH_FLOATS (OFF_H1G + (size_t)NG_MAX * FD)

__device__ float g_scratch[SCRATCH_FLOATS];

// Degree arrays (raw counts, then rsqrt'd in place)
#define DOFF_INVS_CC 0
#define DOFF_INVD_CC (DOFF_INVS_CC + NC_MAX)
#define DOFF_INVS_CG (DOFF_INVD_CC + NC_MAX)
#define DOFF_INVD_CG (DOFF_INVS_CG + NC_MAX)
#define DOFF_INVS_GC (DOFF_INVD_CG + NG_MAX)
#define DOFF_INVD_GC (DOFF_INVS_GC + NG_MAX)
#define DEG_TOTAL    (DOFF_INVD_GC + NC_MAX)

__device__ float g_deg[DEG_TOTAL];

// Int scratch
#define IOFF_RP_CC  0
#define IOFF_CUR_CC (IOFF_RP_CC + NC_MAX + 1)
#define IOFF_RP_GC  (IOFF_CUR_CC + NC_MAX)
#define IOFF_CUR_GC (IOFF_RP_GC + NC_MAX + 1)
#define IOFF_RP_CG  (IOFF_CUR_GC + NC_MAX)
#define IOFF_CUR_CG (IOFF_RP_CG + NG_MAX + 1)
#define IOFF_COL_CC (IOFF_CUR_CG + NG_MAX)
#define IOFF_COL_GC (IOFF_COL_CC + ECC_MAX)
#define IOFF_COL_CG (IOFF_COL_GC + EGC_MAX)
#define IOFF_BSUM   (IOFF_COL_CG + ECG_MAX)
#define INT_TOTAL   (IOFF_BSUM + 128)

__device__ int g_int[INT_TOTAL];

// ---------------------------------------------------------------------------
// Degree histogram: all 3 relations in one launch
// ---------------------------------------------------------------------------
__global__ void deg_all(const int* __restrict__ s0, const int* __restrict__ d0, int n0,
                        float* dS0, float* dD0,
                        const int* __restrict__ s1, const int* __restrict__ d1, int n1,
                        float* dS1, float* dD1,
                        const int* __restrict__ s2, const int* __restrict__ d2, int n2,
                        float* dS2, float* dD2) {
    int i = blockIdx.x * blockDim.x + threadIdx.x;
    if (i < n0) {
        atomicAdd(&dS0[s0[i]], 1.0f);
        atomicAdd(&dD0[d0[i]], 1.0f);
    } else if (i < n0 + n1) {
        int j = i - n0;
        atomicAdd(&dS1[s1[j]], 1.0f);
        atomicAdd(&dD1[d1[j]], 1.0f);
    } else if (i < n0 + n1 + n2) {
        int j = i - n0 - n1;
        atomicAdd(&dS2[s2[j]], 1.0f);
        atomicAdd(&dD2[d2[j]], 1.0f);
    }
}

__global__ void rsqrt_kernel(float* d, int n) {
    int i = blockIdx.x * blockDim.x + threadIdx.x;
    if (i < n) d[i] = rsqrtf(fmaxf(d[i], 1.0f));
}

// ---------------------------------------------------------------------------
// Parallel 3-relation exclusive scan, 3 passes
// ---------------------------------------------------------------------------
#define SCAN_TILE 4096

__global__ __launch_bounds__(256) void scan_pass1(
    const float* c0, int n0, const float* c1, int n1, const float* c2, int n2,
    int nb0, int nb1, int* bsum) {
    int gb = blockIdx.x;
    const float* cnt; int n; int lb;
    if (gb < nb0) { cnt = c0; n = n0; lb = gb; }
    else if (gb < nb0 + nb1) { cnt = c1; n = n1; lb = gb - nb0; }
    else { cnt = c2; n = n2; lb = gb - nb0 - nb1; }

    int base = lb * SCAN_TILE + threadIdx.x * 16;
    int s = 0;
#pragma unroll
    for (int j = 0; j < 16; j++) {
        int i = base + j;
        if (i < n) s += (int)cnt[i];
    }
#pragma unroll
    for (int o = 16; o; o >>= 1) s += __shfl_down_sync(0xffffffffu, s, o);
    __shared__ int ws[8];
    if ((threadIdx.x & 31) == 0) ws[threadIdx.x >> 5] = s;
    __syncthreads();
    if (threadIdx.x == 0) {
        int t = 0;
        for (int w = 0; w < 8; w++) t += ws[w];
        bsum[gb] = t;
    }
}

__global__ void scan_pass2(int* bsum, int nb0, int nb1, int nb2,
                           int* rp0, int n0, int* rp1, int n1, int* rp2, int n2) {
    if (threadIdx.x == 0 && blockIdx.x == 0) {
        int carry = 0;
        for (int i = 0; i < nb0; i++) { int v = bsum[i]; bsum[i] = carry; carry += v; }
        rp0[n0] = carry; carry = 0;
        for (int i = nb0; i < nb0 + nb1; i++) { int v = bsum[i]; bsum[i] = carry; carry += v; }
        rp1[n1] = carry; carry = 0;
        for (int i = nb0 + nb1; i < nb0 + nb1 + nb2; i++) { int v = bsum[i]; bsum[i] = carry; carry += v; }
        rp2[n2] = carry;
    }
}

__global__ __launch_bounds__(256) void scan_pass3(
    const float* c0, int n0, int* rp0, int* cur0,
    const float* c1, int n1, int* rp1, int* cur1,
    const float* c2, int n2, int* rp2, int* cur2,
    int nb0, int nb1, const int* __restrict__ bsum) {
    int gb = blockIdx.x;
    const float* cnt; int n; int lb; int* rp; int* cur;
    if (gb < nb0) { cnt = c0; n = n0; lb = gb; rp = rp0; cur = cur0; }
    else if (gb < nb0 + nb1) { cnt = c1; n = n1; lb = gb - nb0; rp = rp1; cur = cur1; }
    else { cnt = c2; n = n2; lb = gb - nb0 - nb1; rp = rp2; cur = cur2; }

    int base = lb * SCAN_TILE + threadIdx.x * 16;
    int v[16];
    int s = 0;
#pragma unroll
    for (int j = 0; j < 16; j++) {
        int i = base + j;
        v[j] = (i < n) ? (int)cnt[i] : 0;
        s += v[j];
    }
    int lane = threadIdx.x & 31, w = threadIdx.x >> 5;
    int x = s;
#pragma unroll
    for (int o = 1; o < 32; o <<= 1) {
        int y = __shfl_up_sync(0xffffffffu, x, o);
        if (lane >= o) x += y;
    }
    __shared__ int ws[8];
    if (lane == 31) ws[w] = x;
    __syncthreads();
    int woff = 0;
    for (int i = 0; i < w; i++) woff += ws[i];
    int excl = woff + (x - s) + bsum[gb];
#pragma unroll
    for (int j = 0; j < 16; j++) {
        int i = base + j;
        if (i < n) { rp[i] = excl; cur[i] = excl; }
        excl += v[j];
    }
}

// CSR fill: all 3 relations in one launch
__global__ void fill_all(const int* __restrict__ s0, const int* __restrict__ d0, int n0,
                         int* cur0, int* col0,
                         const int* __restrict__ s1, const int* __restrict__ d1, int n1,
                         int* cur1, int* col1,
                         const int* __restrict__ s2, const int* __restrict__ d2, int n2,
                         int* cur2, int* col2) {
    int i = blockIdx.x * blockDim.x + threadIdx.x;
    if (i < n0) {
        int p = atomicAdd(&cur0[d0[i]], 1);
        col0[p] = s0[i];
    } else if (i < n0 + n1) {
        int j = i - n0;
        int p = atomicAdd(&cur1[d1[j]], 1);
        col1[p] = s1[j];
    } else if (i < n0 + n1 + n2) {
        int j = i - n0 - n1;
        int p = atomicAdd(&cur2[d2[j]], 1);
        col2[p] = s2[j];
    }
}

// ---------------------------------------------------------------------------
// TF32 tensor-core GEMM, up to 3 independent segments in one grid.
// C[M,128] = (A[M,128] @ B[128,128]) * rowscale[r]
// 128x128 block tile, 8 warps (4m x 2n), warp tile 32x64, m16n8k8 tf32,
// register-prefetch pipeline over K-chunks of 32.
// ---------------------------------------------------------------------------
__device__ __forceinline__ float f2tf32(float x) {
    uint32_t u;
    asm("cvt.rna.tf32.f32 %0, %1;" : "=r"(u) : "f"(x));
    return __uint_as_float(u);
}

#define KC 32

__global__ __launch_bounds__(256) void sgemm_tf32_3(
    const float* A0, const float* B0, const float* s0, float* C0, int M0, int nb0,
    const float* A1, const float* B1, const float* s1, float* C1, int M1, int nb1,
    const float* A2, const float* B2, const float* s2, float* C2, int M2) {
    __shared__ float As[128][36];
    __shared__ float Bs[KC][136];

    const float *A, *B, *rowscale;
    float* C;
    int M, lb;
    int b = blockIdx.x;
    if (b < nb0) { A = A0; B = B0; rowscale = s0; C = C0; M = M0; lb = b; }
    else if (b < nb0 + nb1) { A = A1; B = B1; rowscale = s1; C = C1; M = M1; lb = b - nb0; }
    else { A = A2; B = B2; rowscale = s2; C = C2; M = M2; lb = b - nb0 - nb1; }

    int tid = threadIdx.x;
    int warp = tid >> 5, lane = tid & 31;
    int wm = (warp >> 1) * 32;
    int wn = (warp & 1) * 64;
    int g = lane >> 2;
    int t = lane & 3;
    int block_row = lb * 128;

    float acc[2][8][4];
#pragma unroll
    for (int i = 0; i < 2; i++)
#pragma unroll
        for (int j = 0; j < 8; j++)
#pragma unroll
            for (int k = 0; k < 4; k++) acc[i][j][k] = 0.0f;

    int ar = tid >> 3;
    int ac = (tid & 7) * 4;
    int br = tid >> 5;
    int bc = (tid & 31) * 4;

    // prefetch registers for the gmem->smem pipeline
    float4 aReg[4], bReg[4];
#pragma unroll
    for (int i = 0; i < 4; i++) {
        int gr = block_row + ar + 32 * i;
        aReg[i] = make_float4(0.f, 0.f, 0.f, 0.f);
        if (gr < M) aReg[i] = *(const float4*)(A + (size_t)gr * 128 + ac);
        bReg[i] = *(const float4*)(B + (size_t)(br + 8 * i) * 128 + bc);
    }

    for (int k0 = 0; k0 < 128; k0 += KC) {
        // store current chunk to smem (with tf32 rounding)
#pragma unroll
        for (int i = 0; i < 4; i++) {
            int r = ar + 32 * i;
            As[r][ac + 0] = f2tf32(aReg[i].x);
            As[r][ac + 1] = f2tf32(aReg[i].y);
            As[r][ac + 2] = f2tf32(aReg[i].z);
            As[r][ac + 3] = f2tf32(aReg[i].w);
            int k = br + 8 * i;
            Bs[k][bc + 0] = f2tf32(bReg[i].x);
            Bs[k][bc + 1] = f2tf32(bReg[i].y);
            Bs[k][bc + 2] = f2tf32(bReg[i].z);
            Bs[k][bc + 3] = f2tf32(bReg[i].w);
        }
        __syncthreads();

        // prefetch next chunk while tensor cores work
        if (k0 + KC < 128) {
#pragma unroll
            for (int i = 0; i < 4; i++) {
                int gr = block_row + ar + 32 * i;
                if (gr < M) aReg[i] = *(const float4*)(A + (size_t)gr * 128 + k0 + KC + ac);
                bReg[i] = *(const float4*)(B + (size_t)(k0 + KC + br + 8 * i) * 128 + bc);
            }
        }

#pragma unroll
        for (int kk = 0; kk < KC; kk += 8) {
            uint32_t af[2][4];
#pragma unroll
            for (int ti = 0; ti < 2; ti++) {
                int row = wm + 16 * ti + g;
                int col = kk + t;
                af[ti][0] = __float_as_uint(As[row][col]);
                af[ti][1] = __float_as_uint(As[row + 8][col]);
                af[ti][2] = __float_as_uint(As[row][col + 4]);
                af[ti][3] = __float_as_uint(As[row + 8][col + 4]);
            }
            uint32_t bf[8][2];
#pragma unroll
            for (int u = 0; u < 8; u++) {
                int k = kk + t;
                int n = wn + 8 * u + g;
                bf[u][0] = __float_as_uint(Bs[k][n]);
                bf[u][1] = __float_as_uint(Bs[k + 4][n]);
            }
#pragma unroll
            for (int ti = 0; ti < 2; ti++)
#pragma unroll
                for (int u = 0; u < 8; u++) {
                    asm volatile(
                        "mma.sync.aligned.m16n8k8.row.col.f32.tf32.tf32.f32 "
                        "{%0,%1,%2,%3}, {%4,%5,%6,%7}, {%8,%9}, {%0,%1,%2,%3};\n"
                        : "+f"(acc[ti][u][0]), "+f"(acc[ti][u][1]),
                          "+f"(acc[ti][u][2]), "+f"(acc[ti][u][3])
                        : "r"(af[ti][0]), "r"(af[ti][1]), "r"(af[ti][2]), "r"(af[ti][3]),
                          "r"(bf[u][0]), "r"(bf[u][1]));
                }
        }
        __syncthreads();
    }

#pragma unroll
    for (int ti = 0; ti < 2; ti++) {
        int row0 = block_row + wm + 16 * ti + g;
        int row1 = row0 + 8;
        float sc0 = (row0 < M) ? rowscale[row0] : 0.f;
        float sc1 = (row1 < M) ? rowscale[row1] : 0.f;
#pragma unroll
        for (int u = 0; u < 8; u++) {
            int cb = wn + 8 * u + 2 * t;
            if (row0 < M) {
                float2 v0 = make_float2(acc[ti][u][0] * sc0, acc[ti][u][1] * sc0);
                *(float2*)(C + (size_t)row0 * 128 + cb) = v0;
            }
            if (row1 < M) {
                float2 v1 = make_float2(acc[ti][u][2] * sc1, acc[ti][u][3] * sc1);
                *(float2*)(C + (size_t)row1 * 128 + cb) = v1;
            }
        }
    }
}

// ---------------------------------------------------------------------------
// Gather helpers: CSR row sum with 4-deep MLP unrolling
// ---------------------------------------------------------------------------
__device__ __forceinline__ float4 csr_rowsum(const int* __restrict__ rp,
                                             const int* __restrict__ col,
                                             const float* __restrict__ feat,
                                             int r, int lo) {
    float4 acc = make_float4(0.f, 0.f, 0.f, 0.f);
    int j = rp[r], e = rp[r + 1];
    for (; j + 3 < e; j += 4) {
        int s0 = col[j], s1 = col[j + 1], s2 = col[j + 2], s3 = col[j + 3];
        float4 v0 = *(const float4*)(feat + (size_t)s0 * FD + lo);
        float4 v1 = *(const float4*)(feat + (size_t)s1 * FD + lo);
        float4 v2 = *(const float4*)(feat + (size_t)s2 * FD + lo);
        float4 v3 = *(const float4*)(feat + (size_t)s3 * FD + lo);
        acc.x += (v0.x + v1.x) + (v2.x + v3.x);
        acc.y += (v0.y + v1.y) + (v2.y + v3.y);
        acc.z += (v0.z + v1.z) + (v2.z + v3.z);
        acc.w += (v0.w + v1.w) + (v2.w + v3.w);
    }
    for (; j < e; j++) {
        int s0 = col[j];
        float4 v0 = *(const float4*)(feat + (size_t)s0 * FD + lo);
        acc.x += v0.x; acc.y += v0.y; acc.z += v0.z; acc.w += v0.w;
    }
    return acc;
}

// Layer-1 fused gather: chem rows (two relations) + gene rows (one relation)
__global__ __launch_bounds__(256) void gather_l1(
    const int* __restrict__ rpA, const int* __restrict__ colA,
    const float* __restrict__ featA, const float* __restrict__ invdA,
    const float* __restrict__ bA,
    const int* __restrict__ rpB, const int* __restrict__ colB,
    const float* __restrict__ featB, const float* __restrict__ invdB,
    const float* __restrict__ bB,
    float* __restrict__ outC, int Nc,
    const int* __restrict__ rpG, const int* __restrict__ colG,
    const float* __restrict__ featG, const float* __restrict__ invdG,
    const float* __restrict__ bG,
    float* __restrict__ outG, int Ng) {
    int r = blockIdx.x * 8 + (threadIdx.x >> 5);
    int lane = threadIdx.x & 31;
    int lo = lane * 4;
    if (r < Nc) {
        float4 a = csr_rowsum(rpA, colA, featA, r, lo);
        float4 b = csr_rowsum(rpB, colB, featB, r, lo);
        float wa = invdA[r], wb = invdB[r];
        float4 ba = *(const float4*)(bA + lo);
        float4 bb = *(const float4*)(bB + lo);
        float4 res = make_float4(a.x * wa + b.x * wb + ba.x + bb.x,
                                 a.y * wa + b.y * wb + ba.y + bb.y,
                                 a.z * wa + b.z * wb + ba.z + bb.z,
                                 a.w * wa + b.w * wb + ba.w + bb.w);
        res.x = res.x > 0.f ? res.x : 0.01f * res.x;
        res.y = res.y > 0.f ? res.y : 0.01f * res.y;
        res.z = res.z > 0.f ? res.z : 0.01f * res.z;
        res.w = res.w > 0.f ? res.w : 0.01f * res.w;
        *(float4*)(outC + (size_t)r * FD + lo) = res;
    } else if (r < Nc + Ng) {
        int rg = r - Nc;
        float4 a = csr_rowsum(rpG, colG, featG, rg, lo);
        float w = invdG[rg];
        float4 bb = *(const float4*)(bG + lo);
        float4 res = make_float4(a.x * w + bb.x, a.y * w + bb.y,
                                 a.z * w + bb.z, a.w * w + bb.w);
        res.x = res.x > 0.f ? res.x : 0.01f * res.x;
        res.y = res.y > 0.f ? res.y : 0.01f * res.y;
        res.z = res.z > 0.f ? res.z : 0.01f * res.z;
        res.w = res.w > 0.f ? res.w : 0.01f * res.w;
        *(float4*)(outG + (size_t)rg * FD + lo) = res;
    }
}

// Layer-2 gather: chem rows only (two relations, no relu)
__global__ __launch_bounds__(256) void gather_l2(
    const int* __restrict__ rpA, const int* __restrict__ colA,
    const float* __restrict__ featA, const float* __restrict__ invdA,
    const float* __restrict__ bA,
    const int* __restrict__ rpB, const int* __restrict__ colB,
    const float* __restrict__ featB, const float* __restrict__ invdB,
    const float* __restrict__ bB,
    float* __restrict__ out, int rows) {
    int r = blockIdx.x * 8 + (threadIdx.x >> 5);
    if (r >= rows) return;
    int lane = threadIdx.x & 31;
    int lo = lane * 4;
    float4 a = csr_rowsum(rpA, colA, featA, r, lo);
    float4 b = csr_rowsum(rpB, colB, featB, r, lo);
    float wa = invdA[r], wb = invdB[r];
    float4 ba = *(const float4*)(bA + lo);
    float4 bb = *(const float4*)(bB + lo);
    float4 res = make_float4(a.x * wa + b.x * wb + ba.x + bb.x,
                             a.y * wa + b.y * wb + ba.y + bb.y,
                             a.z * wa + b.z * wb + ba.z + bb.z,
                             a.w * wa + b.w * wb + ba.w + bb.w);
    *(float4*)(out + (size_t)r * FD + lo) = res;
}

// ---------------------------------------------------------------------------
// Host launch
// ---------------------------------------------------------------------------
extern "C" void kernel_launch(void* const* d_in, const int* in_sizes, int n_in,
                              void* d_out, int out_size) {
    const float* x_chem = (const float*)d_in[0];
    const float* x_gene = (const float*)d_in[1];
    const int* src_cc = (const int*)d_in[2];
    const int* dst_cc = (const int*)d_in[3];
    const int* src_cg = (const int*)d_in[4];
    const int* dst_cg = (const int*)d_in[5];
    const int* src_gc = (const int*)d_in[6];
    const int* dst_gc = (const int*)d_in[7];

    const float *W1_cc, *W1_cg, *W1_gc, *W2_cc, *W2_cg, *W2_gc;
    const float *b1_cc, *b1_cg, *b1_gc, *b2_cc, *b2_cg, *b2_gc;
    if (in_sizes[9] == FD) {  // interleaved
        W1_cc = (const float*)d_in[8];  b1_cc = (const float*)d_in[9];
        W1_cg = (const float*)d_in[10]; b1_cg = (const float*)d_in[11];
        W1_gc = (const float*)d_in[12]; b1_gc = (const float*)d_in[13];
        W2_cc = (const float*)d_in[14]; b2_cc = (const float*)d_in[15];
        W2_cg = (const float*)d_in[16]; b2_cg = (const float*)d_in[17];
        W2_gc = (const float*)d_in[18]; b2_gc = (const float*)d_in[19];
    } else {                  // grouped
        W1_cc = (const float*)d_in[8];
        W1_cg = (const float*)d_in[9];
        W1_gc = (const float*)d_in[10];
        W2_cc = (const float*)d_in[11];
        W2_cg = (const float*)d_in[12];
        W2_gc = (const float*)d_in[13];
        b1_cc = (const float*)d_in[14];
        b1_cg = (const float*)d_in[15];
        b1_gc = (const float*)d_in[16];
        b2_cc = (const float*)d_in[17];
        b2_cg = (const float*)d_in[18];
        b2_gc = (const float*)d_in[19];
    }

    int Nc = in_sizes[0] / FD;
    int Ng = in_sizes[1] / FD;
    int nEcc = in_sizes[2];
    int nEcg = in_sizes[4];
    int nEgc = in_sizes[6];

    float* scratch = nullptr;
    float* deg = nullptr;
    int* ints = nullptr;
    cudaGetSymbolAddress((void**)&scratch, g_scratch);
    cudaGetSymbolAddress((void**)&deg, g_deg);
    cudaGetSymbolAddress((void**)&ints, g_int);

    float* Ycc = scratch + OFF_YCC;
    float* Ycg = scratch + OFF_YCG;
    float* Ygc = scratch + OFF_YGC;
    float* h1c = scratch + OFF_H1C;
    float* h1g = scratch + OFF_H1G;

    float* invs_cc = deg + DOFF_INVS_CC;
    float* invd_cc = deg + DOFF_INVD_CC;
    float* invs_cg = deg + DOFF_INVS_CG;
    float* invd_cg = deg + DOFF_INVD_CG;
    float* invs_gc = deg + DOFF_INVS_GC;
    float* invd_gc = deg + DOFF_INVD_GC;

    int* rp_cc = ints + IOFF_RP_CC;
    int* cur_cc = ints + IOFF_CUR_CC;
    int* rp_gc = ints + IOFF_RP_GC;
    int* cur_gc = ints + IOFF_CUR_GC;
    int* rp_cg = ints + IOFF_RP_CG;
    int* cur_cg = ints + IOFF_CUR_CG;
    int* col_cc = ints + IOFF_COL_CC;
    int* col_gc = ints + IOFF_COL_GC;
    int* col_cg = ints + IOFF_COL_CG;
    int* bsum = ints + IOFF_BSUM;

    float* out = (float*)d_out;

    // ---- degrees ----
    cudaMemsetAsync(deg, 0, DEG_TOTAL * sizeof(float), 0);
    int nEtot = nEcc + nEcg + nEgc;
    deg_all<<<(nEtot + 255) / 256, 256>>>(src_cc, dst_cc, nEcc, invs_cc, invd_cc,
                                          src_cg, dst_cg, nEcg, invs_cg, invd_cg,
                                          src_gc, dst_gc, nEgc, invs_gc, invd_gc);

    // ---- parallel CSR scan over in-degree counts ----
    int nb0 = (Nc + SCAN_TILE - 1) / SCAN_TILE;
    int nb1 = (Nc + SCAN_TILE - 1) / SCAN_TILE;
    int nb2 = (Ng + SCAN_TILE - 1) / SCAN_TILE;
    int nbT = nb0 + nb1 + nb2;
    scan_pass1<<<nbT, 256>>>(invd_cc, Nc, invd_gc, Nc, invd_cg, Ng, nb0, nb1, bsum);
    scan_pass2<<<1, 32>>>(bsum, nb0, nb1, nb2, rp_cc, Nc, rp_gc, Nc, rp_cg, Ng);
    scan_pass3<<<nbT, 256>>>(invd_cc, Nc, rp_cc, cur_cc,
                             invd_gc, Nc, rp_gc, cur_gc,
                             invd_cg, Ng, rp_cg, cur_cg,
                             nb0, nb1, bsum);
    rsqrt_kernel<<<(DEG_TOTAL + 255) / 256, 256>>>(deg, DEG_TOTAL);
    fill_all<<<(nEtot + 255) / 256, 256>>>(src_cc, dst_cc, nEcc, cur_cc, col_cc,
                                           src_gc, dst_gc, nEgc, cur_gc, col_gc,
                                           src_cg, dst_cg, nEcg, cur_cg, col_cg);

    // ---- layer 1: all three GEMMs in one grid ----
    int gBlkC = (Nc + 127) / 128;
    int gBlkG = (Ng + 127) / 128;
    sgemm_tf32_3<<<2 * gBlkC + gBlkG, 256>>>(
        x_chem, W1_cc, invs_cc, Ycc, Nc, gBlkC,
        x_chem, W1_cg, invs_cg, Ycg, Nc, gBlkC,
        x_gene, W1_gc, invs_gc, Ygc, Ng);

    // ---- layer 1: fused gathers (chem + gene) ----
    gather_l1<<<(Nc + Ng + 7) / 8, 256>>>(rp_cc, col_cc, Ycc, invd_cc, b1_cc,
                                          rp_gc, col_gc, Ygc, invd_gc, b1_gc,
                                          h1c, Nc,
                                          rp_cg, col_cg, Ycg, invd_cg, b1_cg,
                                          h1g, Ng);

    // ---- layer 2: both GEMMs in one grid ----
    sgemm_tf32_3<<<gBlkC + gBlkG, 256>>>(
        h1c, W2_cc, invs_cc, Ycc, Nc, gBlkC,
        h1g, W2_gc, invs_gc, Ygc, Ng, gBlkG,
        (const float*)nullptr, (const float*)nullptr, (const float*)nullptr,
        (float*)nullptr, 0);

    // ---- layer 2: gather -> output ----
    gather_l2<<<(Nc + 7) / 8, 256>>>(rp_cc, col_cc, Ycc, invd_cc, b2_cc,
                                     rp_gc, col_gc, Ygc, invd_gc, b2_gc,
                                     out, Nc);
}

// round 5
// speedup vs baseline: 4.7562x; 1.1353x over previous
#include <cuda_runtime.h>
#include <cuda_fp16.h>
#include <cstdint>

// ---------------------------------------------------------------------------
// Problem constants
// ---------------------------------------------------------------------------
#define NC_MAX 50000
#define NG_MAX 30000
#define FD 128
#define ECC_MAX 500000
#define ECG_MAX 400000
#define EGC_MAX 400000

// fp16 feature scratch: Ycc, Ycg (chem rows), Ygc (gene rows), h1c, h1g
#define HOFF_YCC ((size_t)0)
#define HOFF_YCG ((size_t)NC_MAX * FD)
#define HOFF_YGC ((size_t)2 * NC_MAX * FD)
#define HOFF_H1C (HOFF_YGC + (size_t)NG_MAX * FD)
#define HOFF_H1G (HOFF_H1C + (size_t)NC_MAX * FD)
#define HSCRATCH_TOTAL (HOFF_H1G + (size_t)NG_MAX * FD)

__device__ __align__(16) __half g_hscratch[HSCRATCH_TOTAL];

// Degree arrays. Layout: [invs_cc | invs_cg | invs_gc | invd_cc | invd_gc | invd_cg]
// (the three out-degree arrays contiguous so pass3's extra blocks can rsqrt them)
#define DOFF_INVS_CC 0
#define DOFF_INVS_CG (DOFF_INVS_CC + NC_MAX)
#define DOFF_INVS_GC (DOFF_INVS_CG + NC_MAX)
#define INVS_TOTAL   (DOFF_INVS_GC + NG_MAX)
#define DOFF_INVD_CC (INVS_TOTAL)
#define DOFF_INVD_GC (DOFF_INVD_CC + NC_MAX)
#define DOFF_INVD_CG (DOFF_INVD_GC + NC_MAX)
#define DEG_TOTAL    (DOFF_INVD_CG + NG_MAX)

__device__ float g_deg[DEG_TOTAL];

// Int scratch
#define IOFF_RP_CC  0
#define IOFF_CUR_CC (IOFF_RP_CC + NC_MAX + 1)
#define IOFF_RP_GC  (IOFF_CUR_CC + NC_MAX)
#define IOFF_CUR_GC (IOFF_RP_GC + NC_MAX + 1)
#define IOFF_RP_CG  (IOFF_CUR_GC + NC_MAX)
#define IOFF_CUR_CG (IOFF_RP_CG + NG_MAX + 1)
#define IOFF_COL_CC (IOFF_CUR_CG + NG_MAX)
#define IOFF_COL_GC (IOFF_COL_CC + ECC_MAX)
#define IOFF_COL_CG (IOFF_COL_GC + EGC_MAX)
#define IOFF_BSUM   (IOFF_COL_CG + ECG_MAX)
#define INT_TOTAL   (IOFF_BSUM + 256)

__device__ int g_int[INT_TOTAL];

// ---------------------------------------------------------------------------
// Degree histogram: all 3 relations in one launch
// ---------------------------------------------------------------------------
__global__ void deg_all(const int* __restrict__ s0, const int* __restrict__ d0, int n0,
                        float* dS0, float* dD0,
                        const int* __restrict__ s1, const int* __restrict__ d1, int n1,
                        float* dS1, float* dD1,
                        const int* __restrict__ s2, const int* __restrict__ d2, int n2,
                        float* dS2, float* dD2) {
    int i = blockIdx.x * blockDim.x + threadIdx.x;
    if (i < n0) {
        atomicAdd(&dS0[s0[i]], 1.0f);
        atomicAdd(&dD0[d0[i]], 1.0f);
    } else if (i < n0 + n1) {
        int j = i - n0;
        atomicAdd(&dS1[s1[j]], 1.0f);
        atomicAdd(&dD1[d1[j]], 1.0f);
    } else if (i < n0 + n1 + n2) {
        int j = i - n0 - n1;
        atomicAdd(&dS2[s2[j]], 1.0f);
        atomicAdd(&dD2[d2[j]], 1.0f);
    }
}

// ---------------------------------------------------------------------------
// Parallel 3-relation exclusive scan, tile = 1024 (256 thr x 4)
// ---------------------------------------------------------------------------
#define SCAN_TILE 1024

__global__ __launch_bounds__(256) void scan_pass1(
    const float* c0, int n0, const float* c1, int n1, const float* c2, int n2,
    int nb0, int nb1, int* bsum) {
    int gb = blockIdx.x;
    const float* cnt; int n; int lb;
    if (gb < nb0) { cnt = c0; n = n0; lb = gb; }
    else if (gb < nb0 + nb1) { cnt = c1; n = n1; lb = gb - nb0; }
    else { cnt = c2; n = n2; lb = gb - nb0 - nb1; }

    int base = lb * SCAN_TILE + threadIdx.x * 4;
    int s = 0;
#pragma unroll
    for (int j = 0; j < 4; j++) {
        int i = base + j;
        if (i < n) s += (int)cnt[i];
    }
#pragma unroll
    for (int o = 16; o; o >>= 1) s += __shfl_down_sync(0xffffffffu, s, o);
    __shared__ int ws[8];
    if ((threadIdx.x & 31) == 0) ws[threadIdx.x >> 5] = s;
    __syncthreads();
    if (threadIdx.x == 0) {
        int t = 0;
        for (int w = 0; w < 8; w++) t += ws[w];
        bsum[gb] = t;
    }
}

__global__ void scan_pass2(int* bsum, int nb0, int nb1, int nb2,
                           int* rp0, int n0, int* rp1, int n1, int* rp2, int n2) {
    if (threadIdx.x == 0 && blockIdx.x == 0) {
        int carry = 0;
        for (int i = 0; i < nb0; i++) { int v = bsum[i]; bsum[i] = carry; carry += v; }
        rp0[n0] = carry; carry = 0;
        for (int i = nb0; i < nb0 + nb1; i++) { int v = bsum[i]; bsum[i] = carry; carry += v; }
        rp1[n1] = carry; carry = 0;
        for (int i = nb0 + nb1; i < nb0 + nb1 + nb2; i++) { int v = bsum[i]; bsum[i] = carry; carry += v; }
        rp2[n2] = carry;
    }
}

// pass3: scan blocks produce rowptr/cursor AND rewrite the in-degree count
// with rsqrt(max(cnt,1)); extra blocks rsqrt the contiguous out-degree region.
__global__ __launch_bounds__(256) void scan_pass3(
    float* c0, int n0, int* rp0, int* cur0,
    float* c1, int n1, int* rp1, int* cur1,
    float* c2, int n2, int* rp2, int* cur2,
    int nb0, int nb1, int nbT, const int* __restrict__ bsum,
    float* invs_region, int invs_n) {
    int gb = blockIdx.x;
    if (gb >= nbT) {
        int base = (gb - nbT) * SCAN_TILE + threadIdx.x * 4;
#pragma unroll
        for (int j = 0; j < 4; j++) {
            int i = base + j;
            if (i < invs_n) invs_region[i] = rsqrtf(fmaxf(invs_region[i], 1.0f));
        }
        return;
    }
    float* cnt; int n; int lb; int* rp; int* cur;
    if (gb < nb0) { cnt = c0; n = n0; lb = gb; rp = rp0; cur = cur0; }
    else if (gb < nb0 + nb1) { cnt = c1; n = n1; lb = gb - nb0; rp = rp1; cur = cur1; }
    else { cnt = c2; n = n2; lb = gb - nb0 - nb1; rp = rp2; cur = cur2; }

    int base = lb * SCAN_TILE + threadIdx.x * 4;
    int v[4];
    int s = 0;
#pragma unroll
    for (int j = 0; j < 4; j++) {
        int i = base + j;
        v[j] = (i < n) ? (int)cnt[i] : 0;
        s += v[j];
    }
    int lane = threadIdx.x & 31, w = threadIdx.x >> 5;
    int x = s;
#pragma unroll
    for (int o = 1; o < 32; o <<= 1) {
        int y = __shfl_up_sync(0xffffffffu, x, o);
        if (lane >= o) x += y;
    }
    __shared__ int ws[8];
    if (lane == 31) ws[w] = x;
    __syncthreads();
    int woff = 0;
    for (int i = 0; i < w; i++) woff += ws[i];
    int excl = woff + (x - s) + bsum[gb];
#pragma unroll
    for (int j = 0; j < 4; j++) {
        int i = base + j;
        if (i < n) {
            rp[i] = excl;
            cur[i] = excl;
            cnt[i] = rsqrtf(fmaxf((float)v[j], 1.0f));  // becomes invd
        }
        excl += v[j];
    }
}

// CSR fill: all 3 relations in one launch
__global__ void fill_all(const int* __restrict__ s0, const int* __restrict__ d0, int n0,
                         int* cur0, int* col0,
                         const int* __restrict__ s1, const int* __restrict__ d1, int n1,
                         int* cur1, int* col1,
                         const int* __restrict__ s2, const int* __restrict__ d2, int n2,
                         int* cur2, int* col2) {
    int i = blockIdx.x * blockDim.x + threadIdx.x;
    if (i < n0) {
        int p = atomicAdd(&cur0[d0[i]], 1);
        col0[p] = s0[i];
    } else if (i < n0 + n1) {
        int j = i - n0;
        int p = atomicAdd(&cur1[d1[j]], 1);
        col1[p] = s1[j];
    } else if (i < n0 + n1 + n2) {
        int j = i - n0 - n1;
        int p = atomicAdd(&cur2[d2[j]], 1);
        col2[p] = s2[j];
    }
}

// ---------------------------------------------------------------------------
// TF32 tensor-core GEMM, 3 segments per grid, templated input/output types.
// C[M,128] = (A[M,128] @ B[128,128]) * rowscale[r]; C stored fp16.
// ---------------------------------------------------------------------------
__device__ __forceinline__ float f2tf32(float x) {
    uint32_t u;
    asm("cvt.rna.tf32.f32 %0, %1;" : "=r"(u) : "f"(x));
    return __uint_as_float(u);
}

#define KC 32

template <int IN_HALF>
__global__ __launch_bounds__(256) void sgemm_tf32_3(
    const void* A0, const float* B0, const float* s0, __half* C0, int M0, int nb0,
    const void* A1, const float* B1, const float* s1, __half* C1, int M1, int nb1,
    const void* A2, const float* B2, const float* s2, __half* C2, int M2) {
    __shared__ float As[128][36];
    __shared__ float Bs[KC][136];

    const void* A;
    const float *B, *rowscale;
    __half* C;
    int M, lb;
    int b = blockIdx.x;
    if (b < nb0) { A = A0; B = B0; rowscale = s0; C = C0; M = M0; lb = b; }
    else if (b < nb0 + nb1) { A = A1; B = B1; rowscale = s1; C = C1; M = M1; lb = b - nb0; }
    else { A = A2; B = B2; rowscale = s2; C = C2; M = M2; lb = b - nb0 - nb1; }

    int tid = threadIdx.x;
    int warp = tid >> 5, lane = tid & 31;
    int wm = (warp >> 1) * 32;
    int wn = (warp & 1) * 64;
    int g = lane >> 2;
    int t = lane & 3;
    int block_row = lb * 128;

    float acc[2][8][4];
#pragma unroll
    for (int i = 0; i < 2; i++)
#pragma unroll
        for (int j = 0; j < 8; j++)
#pragma unroll
            for (int k = 0; k < 4; k++) acc[i][j][k] = 0.0f;

    int ar = tid >> 3;
    int ac = (tid & 7) * 4;
    int br = tid >> 5;
    int bc = (tid & 31) * 4;

    // register prefetch
    float4 aReg[4], bReg[4];
#pragma unroll
    for (int i = 0; i < 4; i++) {
        int gr = block_row + ar + 32 * i;
        aReg[i] = make_float4(0.f, 0.f, 0.f, 0.f);
        if (gr < M) {
            if (IN_HALF) {
                uint2 u = *(const uint2*)((const __half*)A + (size_t)gr * 128 + ac);
                float2 f0 = __half22float2(*(__half2*)&u.x);
                float2 f1 = __half22float2(*(__half2*)&u.y);
                aReg[i] = make_float4(f0.x, f0.y, f1.x, f1.y);
            } else {
                aReg[i] = *(const float4*)((const float*)A + (size_t)gr * 128 + ac);
            }
        }
        bReg[i] = *(const float4*)(B + (size_t)(br + 8 * i) * 128 + bc);
    }

    for (int k0 = 0; k0 < 128; k0 += KC) {
#pragma unroll
        for (int i = 0; i < 4; i++) {
            int r = ar + 32 * i;
            if (IN_HALF) {  // fp16 values are exactly representable in tf32
                As[r][ac + 0] = aReg[i].x;
                As[r][ac + 1] = aReg[i].y;
                As[r][ac + 2] = aReg[i].z;
                As[r][ac + 3] = aReg[i].w;
            } else {
                As[r][ac + 0] = f2tf32(aReg[i].x);
                As[r][ac + 1] = f2tf32(aReg[i].y);
                As[r][ac + 2] = f2tf32(aReg[i].z);
                As[r][ac + 3] = f2tf32(aReg[i].w);
            }
            int k = br + 8 * i;
            Bs[k][bc + 0] = f2tf32(bReg[i].x);
            Bs[k][bc + 1] = f2tf32(bReg[i].y);
            Bs[k][bc + 2] = f2tf32(bReg[i].z);
            Bs[k][bc + 3] = f2tf32(bReg[i].w);
        }
        __syncthreads();

        if (k0 + KC < 128) {
#pragma unroll
            for (int i = 0; i < 4; i++) {
                int gr = block_row + ar + 32 * i;
                if (gr < M) {
                    if (IN_HALF) {
                        uint2 u = *(const uint2*)((const __half*)A + (size_t)gr * 128 + k0 + KC + ac);
                        float2 f0 = __half22float2(*(__half2*)&u.x);
                        float2 f1 = __half22float2(*(__half2*)&u.y);
                        aReg[i] = make_float4(f0.x, f0.y, f1.x, f1.y);
                    } else {
                        aReg[i] = *(const float4*)((const float*)A + (size_t)gr * 128 + k0 + KC + ac);
                    }
                }
                bReg[i] = *(const float4*)(B + (size_t)(k0 + KC + br + 8 * i) * 128 + bc);
            }
        }

#pragma unroll
        for (int kk = 0; kk < KC; kk += 8) {
            uint32_t af[2][4];
#pragma unroll
            for (int ti = 0; ti < 2; ti++) {
                int row = wm + 16 * ti + g;
                int col = kk + t;
                af[ti][0] = __float_as_uint(As[row][col]);
                af[ti][1] = __float_as_uint(As[row + 8][col]);
                af[ti][2] = __float_as_uint(As[row][col + 4]);
                af[ti][3] = __float_as_uint(As[row + 8][col + 4]);
            }
            uint32_t bf[8][2];
#pragma unroll
            for (int u = 0; u < 8; u++) {
                int k = kk + t;
                int n = wn + 8 * u + g;
                bf[u][0] = __float_as_uint(Bs[k][n]);
                bf[u][1] = __float_as_uint(Bs[k + 4][n]);
            }
#pragma unroll
            for (int ti = 0; ti < 2; ti++)
#pragma unroll
                for (int u = 0; u < 8; u++) {
                    asm volatile(
                        "mma.sync.aligned.m16n8k8.row.col.f32.tf32.tf32.f32 "
                        "{%0,%1,%2,%3}, {%4,%5,%6,%7}, {%8,%9}, {%0,%1,%2,%3};\n"
                        : "+f"(acc[ti][u][0]), "+f"(acc[ti][u][1]),
                          "+f"(acc[ti][u][2]), "+f"(acc[ti][u][3])
                        : "r"(af[ti][0]), "r"(af[ti][1]), "r"(af[ti][2]), "r"(af[ti][3]),
                          "r"(bf[u][0]), "r"(bf[u][1]));
                }
        }
        __syncthreads();
    }

#pragma unroll
    for (int ti = 0; ti < 2; ti++) {
        int row0 = block_row + wm + 16 * ti + g;
        int row1 = row0 + 8;
        float sc0 = (row0 < M) ? rowscale[row0] : 0.f;
        float sc1 = (row1 < M) ? rowscale[row1] : 0.f;
#pragma unroll
        for (int u = 0; u < 8; u++) {
            int cb = wn + 8 * u + 2 * t;
            if (row0 < M)
                *(__half2*)(C + (size_t)row0 * 128 + cb) =
                    __floats2half2_rn(acc[ti][u][0] * sc0, acc[ti][u][1] * sc0);
            if (row1 < M)
                *(__half2*)(C + (size_t)row1 * 128 + cb) =
                    __floats2half2_rn(acc[ti][u][2] * sc1, acc[ti][u][3] * sc1);
        }
    }
}

// ---------------------------------------------------------------------------
// Gather: CSR row sum over fp16 features, fp32 accumulation, 4-edge MLP unroll
// ---------------------------------------------------------------------------
__device__ __forceinline__ void csr_rowsum_h(const int* __restrict__ rp,
                                             const int* __restrict__ col,
                                             const __half* __restrict__ feat,
                                             int r, int lo, float4& acc) {
    acc = make_float4(0.f, 0.f, 0.f, 0.f);
    int j = rp[r], e = rp[r + 1];
    for (; j + 3 < e; j += 4) {
        int s0 = col[j], s1 = col[j + 1], s2 = col[j + 2], s3 = col[j + 3];
        uint2 u0 = *(const uint2*)(feat + (size_t)s0 * FD + lo);
        uint2 u1 = *(const uint2*)(feat + (size_t)s1 * FD + lo);
        uint2 u2 = *(const uint2*)(feat + (size_t)s2 * FD + lo);
        uint2 u3 = *(const uint2*)(feat + (size_t)s3 * FD + lo);
        float2 a0 = __half22float2(*(__half2*)&u0.x), b0 = __half22float2(*(__half2*)&u0.y);
        float2 a1 = __half22float2(*(__half2*)&u1.x), b1 = __half22float2(*(__half2*)&u1.y);
        float2 a2 = __half22float2(*(__half2*)&u2.x), b2 = __half22float2(*(__half2*)&u2.y);
        float2 a3 = __half22float2(*(__half2*)&u3.x), b3 = __half22float2(*(__half2*)&u3.y);
        acc.x += (a0.x + a1.x) + (a2.x + a3.x);
        acc.y += (a0.y + a1.y) + (a2.y + a3.y);
        acc.z += (b0.x + b1.x) + (b2.x + b3.x);
        acc.w += (b0.y + b1.y) + (b2.y + b3.y);
    }
    for (; j < e; j++) {
        int s0 = col[j];
        uint2 u0 = *(const uint2*)(feat + (size_t)s0 * FD + lo);
        float2 a0 = __half22float2(*(__half2*)&u0.x), b0 = __half22float2(*(__half2*)&u0.y);
        acc.x += a0.x; acc.y += a0.y; acc.z += b0.x; acc.w += b0.y;
    }
}

// Layer-1 fused gather: chem rows (two relations, relu, fp16 out)
//                     + gene rows (one relation, relu, fp16 out)
__global__ __launch_bounds__(256) void gather_l1(
    const int* __restrict__ rpA, const int* __restrict__ colA,
    const __half* __restrict__ featA, const float* __restrict__ invdA,
    const float* __restrict__ bA,
    const int* __restrict__ rpB, const int* __restrict__ colB,
    const __half* __restrict__ featB, const float* __restrict__ invdB,
    const float* __restrict__ bB,
    __half* __restrict__ outC, int Nc,
    const int* __restrict__ rpG, const int* __restrict__ colG,
    const __half* __restrict__ featG, const float* __restrict__ invdG,
    const float* __restrict__ bG,
    __half* __restrict__ outG, int Ng) {
    int r = blockIdx.x * 8 + (threadIdx.x >> 5);
    int lane = threadIdx.x & 31;
    int lo = lane * 4;
    float4 res;
    __half* optr;
    if (r < Nc) {
        float4 a, b;
        csr_rowsum_h(rpA, colA, featA, r, lo, a);
        csr_rowsum_h(rpB, colB, featB, r, lo, b);
        float wa = invdA[r], wb = invdB[r];
        float4 ba = *(const float4*)(bA + lo);
        float4 bb = *(const float4*)(bB + lo);
        res = make_float4(a.x * wa + b.x * wb + ba.x + bb.x,
                          a.y * wa + b.y * wb + ba.y + bb.y,
                          a.z * wa + b.z * wb + ba.z + bb.z,
                          a.w * wa + b.w * wb + ba.w + bb.w);
        optr = outC + (size_t)r * FD + lo;
    } else if (r < Nc + Ng) {
        int rg = r - Nc;
        float4 a;
        csr_rowsum_h(rpG, colG, featG, rg, lo, a);
        float w = invdG[rg];
        float4 bb = *(const float4*)(bG + lo);
        res = make_float4(a.x * w + bb.x, a.y * w + bb.y,
                          a.z * w + bb.z, a.w * w + bb.w);
        optr = outG + (size_t)rg * FD + lo;
    } else {
        return;
    }
    res.x = res.x > 0.f ? res.x : 0.01f * res.x;
    res.y = res.y > 0.f ? res.y : 0.01f * res.y;
    res.z = res.z > 0.f ? res.z : 0.01f * res.z;
    res.w = res.w > 0.f ? res.w : 0.01f * res.w;
    *(__half2*)(optr + 0) = __floats2half2_rn(res.x, res.y);
    *(__half2*)(optr + 2) = __floats2half2_rn(res.z, res.w);
}

// Layer-2 gather: chem rows, two relations, fp32 out, no relu
__global__ __launch_bounds__(256) void gather_l2(
    const int* __restrict__ rpA, const int* __restrict__ colA,
    const __half* __restrict__ featA, const float* __restrict__ invdA,
    const float* __restrict__ bA,
    const int* __restrict__ rpB, const int* __restrict__ colB,
    const __half* __restrict__ featB, const float* __restrict__ invdB,
    const float* __restrict__ bB,
    float* __restrict__ out, int rows) {
    int r = blockIdx.x * 8 + (threadIdx.x >> 5);
    if (r >= rows) return;
    int lane = threadIdx.x & 31;
    int lo = lane * 4;
    float4 a, b;
    csr_rowsum_h(rpA, colA, featA, r, lo, a);
    csr_rowsum_h(rpB, colB, featB, r, lo, b);
    float wa = invdA[r], wb = invdB[r];
    float4 ba = *(const float4*)(bA + lo);
    float4 bb = *(const float4*)(bB + lo);
    float4 res = make_float4(a.x * wa + b.x * wb + ba.x + bb.x,
                             a.y * wa + b.y * wb + ba.y + bb.y,
                             a.z * wa + b.z * wb + ba.z + bb.z,
                             a.w * wa + b.w * wb + ba.w + bb.w);
    *(float4*)(out + (size_t)r * FD + lo) = res;
}

// ---------------------------------------------------------------------------
// Host launch
// ---------------------------------------------------------------------------
extern "C" void kernel_launch(void* const* d_in, const int* in_sizes, int n_in,
                              void* d_out, int out_size) {
    const float* x_chem = (const float*)d_in[0];
    const float* x_gene = (const float*)d_in[1];
    const int* src_cc = (const int*)d_in[2];
    const int* dst_cc = (const int*)d_in[3];
    const int* src_cg = (const int*)d_in[4];
    const int* dst_cg = (const int*)d_in[5];
    const int* src_gc = (const int*)d_in[6];
    const int* dst_gc = (const int*)d_in[7];

    const float *W1_cc, *W1_cg, *W1_gc, *W2_cc, *W2_cg, *W2_gc;
    const float *b1_cc, *b1_cg, *b1_gc, *b2_cc, *b2_cg, *b2_gc;
    if (in_sizes[9] == FD) {  // interleaved
        W1_cc = (const float*)d_in[8];  b1_cc = (const float*)d_in[9];
        W1_cg = (const float*)d_in[10]; b1_cg = (const float*)d_in[11];
        W1_gc = (const float*)d_in[12]; b1_gc = (const float*)d_in[13];
        W2_cc = (const float*)d_in[14]; b2_cc = (const float*)d_in[15];
        W2_cg = (const float*)d_in[16]; b2_cg = (const float*)d_in[17];
        W2_gc = (const float*)d_in[18]; b2_gc = (const float*)d_in[19];
    } else {                  // grouped
        W1_cc = (const float*)d_in[8];
        W1_cg = (const float*)d_in[9];
        W1_gc = (const float*)d_in[10];
        W2_cc = (const float*)d_in[11];
        W2_cg = (const float*)d_in[12];
        W2_gc = (const float*)d_in[13];
        b1_cc = (const float*)d_in[14];
        b1_cg = (const float*)d_in[15];
        b1_gc = (const float*)d_in[16];
        b2_cc = (const float*)d_in[17];
        b2_cg = (const float*)d_in[18];
        b2_gc = (const float*)d_in[19];
    }

    int Nc = in_sizes[0] / FD;
    int Ng = in_sizes[1] / FD;
    int nEcc = in_sizes[2];
    int nEcg = in_sizes[4];
    int nEgc = in_sizes[6];

    __half* hs = nullptr;
    float* deg = nullptr;
    int* ints = nullptr;
    cudaGetSymbolAddress((void**)&hs, g_hscratch);
    cudaGetSymbolAddress((void**)&deg, g_deg);
    cudaGetSymbolAddress((void**)&ints, g_int);

    __half* Ycc = hs + HOFF_YCC;
    __half* Ycg = hs + HOFF_YCG;
    __half* Ygc = hs + HOFF_YGC;
    __half* h1c = hs + HOFF_H1C;
    __half* h1g = hs + HOFF_H1G;

    float* invs_cc = deg + DOFF_INVS_CC;
    float* invs_cg = deg + DOFF_INVS_CG;
    float* invs_gc = deg + DOFF_INVS_GC;
    float* invd_cc = deg + DOFF_INVD_CC;
    float* invd_gc = deg + DOFF_INVD_GC;
    float* invd_cg = deg + DOFF_INVD_CG;

    int* rp_cc = ints + IOFF_RP_CC;
    int* cur_cc = ints + IOFF_CUR_CC;
    int* rp_gc = ints + IOFF_RP_GC;
    int* cur_gc = ints + IOFF_CUR_GC;
    int* rp_cg = ints + IOFF_RP_CG;
    int* cur_cg = ints + IOFF_CUR_CG;
    int* col_cc = ints + IOFF_COL_CC;
    int* col_gc = ints + IOFF_COL_GC;
    int* col_cg = ints + IOFF_COL_CG;
    int* bsum = ints + IOFF_BSUM;

    float* out = (float*)d_out;

    // ---- degrees ----
    cudaMemsetAsync(deg, 0, DEG_TOTAL * sizeof(float), 0);
    int nEtot = nEcc + nEcg + nEgc;
    deg_all<<<(nEtot + 255) / 256, 256>>>(src_cc, dst_cc, nEcc, invs_cc, invd_cc,
                                          src_cg, dst_cg, nEcg, invs_cg, invd_cg,
                                          src_gc, dst_gc, nEgc, invs_gc, invd_gc);

    // ---- CSR scan (+ fused rsqrt) ----
    int nb0 = (Nc + SCAN_TILE - 1) / SCAN_TILE;
    int nb1 = (Nc + SCAN_TILE - 1) / SCAN_TILE;
    int nb2 = (Ng + SCAN_TILE - 1) / SCAN_TILE;
    int nbT = nb0 + nb1 + nb2;
    int nrs = (INVS_TOTAL + SCAN_TILE - 1) / SCAN_TILE;
    scan_pass1<<<nbT, 256>>>(invd_cc, Nc, invd_gc, Nc, invd_cg, Ng, nb0, nb1, bsum);
    scan_pass2<<<1, 32>>>(bsum, nb0, nb1, nb2, rp_cc, Nc, rp_gc, Nc, rp_cg, Ng);
    scan_pass3<<<nbT + nrs, 256>>>(invd_cc, Nc, rp_cc, cur_cc,
                                   invd_gc, Nc, rp_gc, cur_gc,
                                   invd_cg, Ng, rp_cg, cur_cg,
                                   nb0, nb1, nbT, bsum,
                                   deg, INVS_TOTAL);
    fill_all<<<(nEtot + 255) / 256, 256>>>(src_cc, dst_cc, nEcc, cur_cc, col_cc,
                                           src_gc, dst_gc, nEgc, cur_gc, col_gc,
                                           src_cg, dst_cg, nEcg, cur_cg, col_cg);

    // ---- layer 1: all three GEMMs in one grid (fp32 in, fp16 out) ----
    int gBlkC = (Nc + 127) / 128;
    int gBlkG = (Ng + 127) / 128;
    sgemm_tf32_3<0><<<2 * gBlkC + gBlkG, 256>>>(
        x_chem, W1_cc, invs_cc, Ycc, Nc, gBlkC,
        x_chem, W1_cg, invs_cg, Ycg, Nc, gBlkC,
        x_gene, W1_gc, invs_gc, Ygc, Ng);

    // ---- layer 1: fused gathers ----
    gather_l1<<<(Nc + Ng + 7) / 8, 256>>>(rp_cc, col_cc, Ycc, invd_cc, b1_cc,
                                          rp_gc, col_gc, Ygc, invd_gc, b1_gc,
                                          h1c, Nc,
                                          rp_cg, col_cg, Ycg, invd_cg, b1_cg,
                                          h1g, Ng);

    // ---- layer 2: both GEMMs in one grid (fp16 in, fp16 out) ----
    sgemm_tf32_3<1><<<gBlkC + gBlkG, 256>>>(
        h1c, W2_cc, invs_cc, Ycc, Nc, gBlkC,
        h1g, W2_gc, invs_gc, Ygc, Ng, gBlkG,
        (const void*)nullptr, (const float*)nullptr, (const float*)nullptr,
        (__half*)nullptr, 0);

    // ---- layer 2: gather -> fp32 output ----
    gather_l2<<<(Nc + 7) / 8, 256>>>(rp_cc, col_cc, Ycc, invd_cc, b2_cc,
                                     rp_gc, col_gc, Ygc, invd_gc, b2_gc,
                                     out, Nc);
}

// round 6
// speedup vs baseline: 5.1353x; 1.0797x over previous
#include <cuda_runtime.h>
#include <cuda_fp16.h>
#include <cstdint>

// ---------------------------------------------------------------------------
// Problem constants
// ---------------------------------------------------------------------------
#define NC_MAX 50000
#define NG_MAX 30000
#define FD 128
#define ECC_MAX 500000
#define ECG_MAX 400000
#define EGC_MAX 400000

// fp16 feature scratch: Ycc, Ycg (chem rows), Ygc (gene rows), h1c, h1g
#define HOFF_YCC ((size_t)0)
#define HOFF_YCG ((size_t)NC_MAX * FD)
#define HOFF_YGC ((size_t)2 * NC_MAX * FD)
#define HOFF_H1C (HOFF_YGC + (size_t)NG_MAX * FD)
#define HOFF_H1G (HOFF_H1C + (size_t)NC_MAX * FD)
#define HSCRATCH_TOTAL (HOFF_H1G + (size_t)NG_MAX * FD)

__device__ __align__(16) __half g_hscratch[HSCRATCH_TOTAL];

// Degree arrays. Layout: [invs_cc | invs_cg | invs_gc | invd_cc | invd_gc | invd_cg]
#define DOFF_INVS_CC 0
#define DOFF_INVS_CG (DOFF_INVS_CC + NC_MAX)
#define DOFF_INVS_GC (DOFF_INVS_CG + NC_MAX)
#define INVS_TOTAL   (DOFF_INVS_GC + NG_MAX)
#define DOFF_INVD_CC (INVS_TOTAL)
#define DOFF_INVD_GC (DOFF_INVD_CC + NC_MAX)
#define DOFF_INVD_CG (DOFF_INVD_GC + NC_MAX)
#define DEG_TOTAL    (DOFF_INVD_CG + NG_MAX)

__device__ float g_deg[DEG_TOTAL];

// Int scratch
#define IOFF_RP_CC  0
#define IOFF_CUR_CC (IOFF_RP_CC + NC_MAX + 1)
#define IOFF_RP_GC  (IOFF_CUR_CC + NC_MAX)
#define IOFF_CUR_GC (IOFF_RP_GC + NC_MAX + 1)
#define IOFF_RP_CG  (IOFF_CUR_GC + NC_MAX)
#define IOFF_CUR_CG (IOFF_RP_CG + NG_MAX + 1)
#define IOFF_COL_CC (IOFF_CUR_CG + NG_MAX)
#define IOFF_COL_GC (IOFF_COL_CC + ECC_MAX)
#define IOFF_COL_CG (IOFF_COL_GC + EGC_MAX)
#define IOFF_BSUM   (IOFF_COL_CG + ECG_MAX)
#define INT_TOTAL   (IOFF_BSUM + 256)

__device__ int g_int[INT_TOTAL];

// ---------------------------------------------------------------------------
// Degree histogram: all 3 relations in one launch
// ---------------------------------------------------------------------------
__global__ void deg_all(const int* __restrict__ s0, const int* __restrict__ d0, int n0,
                        float* dS0, float* dD0,
                        const int* __restrict__ s1, const int* __restrict__ d1, int n1,
                        float* dS1, float* dD1,
                        const int* __restrict__ s2, const int* __restrict__ d2, int n2,
                        float* dS2, float* dD2) {
    int i = blockIdx.x * blockDim.x + threadIdx.x;
    if (i < n0) {
        atomicAdd(&dS0[s0[i]], 1.0f);
        atomicAdd(&dD0[d0[i]], 1.0f);
    } else if (i < n0 + n1) {
        int j = i - n0;
        atomicAdd(&dS1[s1[j]], 1.0f);
        atomicAdd(&dD1[d1[j]], 1.0f);
    } else if (i < n0 + n1 + n2) {
        int j = i - n0 - n1;
        atomicAdd(&dS2[s2[j]], 1.0f);
        atomicAdd(&dD2[d2[j]], 1.0f);
    }
}

// ---------------------------------------------------------------------------
// Parallel 3-relation exclusive scan, tile = 1024 (256 thr x 4)
// ---------------------------------------------------------------------------
#define SCAN_TILE 1024

__global__ __launch_bounds__(256) void scan_pass1(
    const float* c0, int n0, const float* c1, int n1, const float* c2, int n2,
    int nb0, int nb1, int* bsum) {
    int gb = blockIdx.x;
    const float* cnt; int n; int lb;
    if (gb < nb0) { cnt = c0; n = n0; lb = gb; }
    else if (gb < nb0 + nb1) { cnt = c1; n = n1; lb = gb - nb0; }
    else { cnt = c2; n = n2; lb = gb - nb0 - nb1; }

    int base = lb * SCAN_TILE + threadIdx.x * 4;
    int s = 0;
#pragma unroll
    for (int j = 0; j < 4; j++) {
        int i = base + j;
        if (i < n) s += (int)cnt[i];
    }
#pragma unroll
    for (int o = 16; o; o >>= 1) s += __shfl_down_sync(0xffffffffu, s, o);
    __shared__ int ws[8];
    if ((threadIdx.x & 31) == 0) ws[threadIdx.x >> 5] = s;
    __syncthreads();
    if (threadIdx.x == 0) {
        int t = 0;
        for (int w = 0; w < 8; w++) t += ws[w];
        bsum[gb] = t;
    }
}

__global__ void scan_pass2(int* bsum, int nb0, int nb1, int nb2,
                           int* rp0, int n0, int* rp1, int n1, int* rp2, int n2) {
    if (threadIdx.x == 0 && blockIdx.x == 0) {
        int carry = 0;
        for (int i = 0; i < nb0; i++) { int v = bsum[i]; bsum[i] = carry; carry += v; }
        rp0[n0] = carry; carry = 0;
        for (int i = nb0; i < nb0 + nb1; i++) { int v = bsum[i]; bsum[i] = carry; carry += v; }
        rp1[n1] = carry; carry = 0;
        for (int i = nb0 + nb1; i < nb0 + nb1 + nb2; i++) { int v = bsum[i]; bsum[i] = carry; carry += v; }
        rp2[n2] = carry;
    }
}

// pass3: scan blocks produce rowptr/cursor AND rewrite the in-degree count
// with rsqrt(max(cnt,1)); extra blocks rsqrt the contiguous out-degree region.
__global__ __launch_bounds__(256) void scan_pass3(
    float* c0, int n0, int* rp0, int* cur0,
    float* c1, int n1, int* rp1, int* cur1,
    float* c2, int n2, int* rp2, int* cur2,
    int nb0, int nb1, int nbT, const int* __restrict__ bsum,
    float* invs_region, int invs_n) {
    int gb = blockIdx.x;
    if (gb >= nbT) {
        int base = (gb - nbT) * SCAN_TILE + threadIdx.x * 4;
#pragma unroll
        for (int j = 0; j < 4; j++) {
            int i = base + j;
            if (i < invs_n) invs_region[i] = rsqrtf(fmaxf(invs_region[i], 1.0f));
        }
        return;
    }
    float* cnt; int n; int lb; int* rp; int* cur;
    if (gb < nb0) { cnt = c0; n = n0; lb = gb; rp = rp0; cur = cur0; }
    else if (gb < nb0 + nb1) { cnt = c1; n = n1; lb = gb - nb0; rp = rp1; cur = cur1; }
    else { cnt = c2; n = n2; lb = gb - nb0 - nb1; rp = rp2; cur = cur2; }

    int base = lb * SCAN_TILE + threadIdx.x * 4;
    int v[4];
    int s = 0;
#pragma unroll
    for (int j = 0; j < 4; j++) {
        int i = base + j;
        v[j] = (i < n) ? (int)cnt[i] : 0;
        s += v[j];
    }
    int lane = threadIdx.x & 31, w = threadIdx.x >> 5;
    int x = s;
#pragma unroll
    for (int o = 1; o < 32; o <<= 1) {
        int y = __shfl_up_sync(0xffffffffu, x, o);
        if (lane >= o) x += y;
    }
    __shared__ int ws[8];
    if (lane == 31) ws[w] = x;
    __syncthreads();
    int woff = 0;
    for (int i = 0; i < w; i++) woff += ws[i];
    int excl = woff + (x - s) + bsum[gb];
#pragma unroll
    for (int j = 0; j < 4; j++) {
        int i = base + j;
        if (i < n) {
            rp[i] = excl;
            cur[i] = excl;
            cnt[i] = rsqrtf(fmaxf((float)v[j], 1.0f));  // becomes invd
        }
        excl += v[j];
    }
}

// CSR fill: all 3 relations in one launch
__global__ void fill_all(const int* __restrict__ s0, const int* __restrict__ d0, int n0,
                         int* cur0, int* col0,
                         const int* __restrict__ s1, const int* __restrict__ d1, int n1,
                         int* cur1, int* col1,
                         const int* __restrict__ s2, const int* __restrict__ d2, int n2,
                         int* cur2, int* col2) {
    int i = blockIdx.x * blockDim.x + threadIdx.x;
    if (i < n0) {
        int p = atomicAdd(&cur0[d0[i]], 1);
        col0[p] = s0[i];
    } else if (i < n0 + n1) {
        int j = i - n0;
        int p = atomicAdd(&cur1[d1[j]], 1);
        col1[p] = s1[j];
    } else if (i < n0 + n1 + n2) {
        int j = i - n0 - n1;
        int p = atomicAdd(&cur2[d2[j]], 1);
        col2[p] = s2[j];
    }
}

// ---------------------------------------------------------------------------
// FP16 tensor-core GEMM (m16n8k16), 3 segments per grid.
// C[M,128] = (A[M,128] @ B[128,128]) * rowscale[r]; C stored fp16.
// A: fp32 (IN_HALF=0, converted on load) or fp16 (IN_HALF=1). B: fp32 -> fp16.
// Block tile 128x128, 8 warps (4m x 2n), warp tile 32x64, K-chunk 32.
// Smem: As[128][40] halves (frag bank 20g+t mod 32 bijective),
//       Bs2[16][136] half2 packing (k,k+1) (frag bank 8t+g bijective).
// ---------------------------------------------------------------------------
#define KC 32

template <int IN_HALF>
__global__ __launch_bounds__(256) void sgemm_h16_3(
    const void* A0, const float* B0, const float* s0, __half* C0, int M0, int nb0,
    const void* A1, const float* B1, const float* s1, __half* C1, int M1, int nb1,
    const void* A2, const float* B2, const float* s2, __half* C2, int M2) {
    __shared__ __half As[128][40];
    __shared__ __half2 Bs2[KC / 2][136];

    const void* A;
    const float *B, *rowscale;
    __half* C;
    int M, lb;
    int b = blockIdx.x;
    if (b < nb0) { A = A0; B = B0; rowscale = s0; C = C0; M = M0; lb = b; }
    else if (b < nb0 + nb1) { A = A1; B = B1; rowscale = s1; C = C1; M = M1; lb = b - nb0; }
    else { A = A2; B = B2; rowscale = s2; C = C2; M = M2; lb = b - nb0 - nb1; }

    int tid = threadIdx.x;
    int warp = tid >> 5, lane = tid & 31;
    int wm = (warp >> 1) * 32;
    int wn = (warp & 1) * 64;
    int g = lane >> 2;
    int t = lane & 3;
    int block_row = lb * 128;

    float acc[2][8][4];
#pragma unroll
    for (int i = 0; i < 2; i++)
#pragma unroll
        for (int j = 0; j < 8; j++)
#pragma unroll
            for (int k = 0; k < 4; k++) acc[i][j][k] = 0.0f;

    // A loading: 128 rows x 32 cols; thread -> row ar+32i, 4 cols at ac
    int ar = tid >> 3;
    int ac = (tid & 7) * 4;
    // B loading: k-pair kp = (tid>>5) + 8i (i=0,1), 4 n at bn
    int kp = tid >> 5;
    int bn = (tid & 31) * 4;

    // register prefetch buffers
    float4 aReg[4];
    uint2 aRegH[4];
    float4 bRegLo[2], bRegHi[2];

#pragma unroll
    for (int i = 0; i < 4; i++) {
        int gr = block_row + ar + 32 * i;
        if (IN_HALF) {
            aRegH[i] = make_uint2(0u, 0u);
            if (gr < M) aRegH[i] = *(const uint2*)((const __half*)A + (size_t)gr * 128 + ac);
        } else {
            aReg[i] = make_float4(0.f, 0.f, 0.f, 0.f);
            if (gr < M) aReg[i] = *(const float4*)((const float*)A + (size_t)gr * 128 + ac);
        }
    }
#pragma unroll
    for (int i = 0; i < 2; i++) {
        int k = 2 * (kp + 8 * i);
        bRegLo[i] = *(const float4*)(B + (size_t)k * 128 + bn);
        bRegHi[i] = *(const float4*)(B + (size_t)(k + 1) * 128 + bn);
    }

    for (int k0 = 0; k0 < 128; k0 += KC) {
        // ---- store current chunk to smem ----
#pragma unroll
        for (int i = 0; i < 4; i++) {
            int r = ar + 32 * i;
            __half2 h0, h1;
            if (IN_HALF) {
                h0 = *(__half2*)&aRegH[i].x;
                h1 = *(__half2*)&aRegH[i].y;
            } else {
                h0 = __floats2half2_rn(aReg[i].x, aReg[i].y);
                h1 = __floats2half2_rn(aReg[i].z, aReg[i].w);
            }
            *(__half2*)&As[r][ac + 0] = h0;
            *(__half2*)&As[r][ac + 2] = h1;
        }
#pragma unroll
        for (int i = 0; i < 2; i++) {
            int p = kp + 8 * i;
            __half2 q0 = __floats2half2_rn(bRegLo[i].x, bRegHi[i].x);
            __half2 q1 = __floats2half2_rn(bRegLo[i].y, bRegHi[i].y);
            __half2 q2 = __floats2half2_rn(bRegLo[i].z, bRegHi[i].z);
            __half2 q3 = __floats2half2_rn(bRegLo[i].w, bRegHi[i].w);
            Bs2[p][bn + 0] = q0;
            Bs2[p][bn + 1] = q1;
            Bs2[p][bn + 2] = q2;
            Bs2[p][bn + 3] = q3;
        }
        __syncthreads();

        // ---- prefetch next chunk ----
        if (k0 + KC < 128) {
#pragma unroll
            for (int i = 0; i < 4; i++) {
                int gr = block_row + ar + 32 * i;
                if (gr < M) {
                    if (IN_HALF)
                        aRegH[i] = *(const uint2*)((const __half*)A + (size_t)gr * 128 + k0 + KC + ac);
                    else
                        aReg[i] = *(const float4*)((const float*)A + (size_t)gr * 128 + k0 + KC + ac);
                }
            }
#pragma unroll
            for (int i = 0; i < 2; i++) {
                int k = k0 + KC + 2 * (kp + 8 * i);
                bRegLo[i] = *(const float4*)(B + (size_t)k * 128 + bn);
                bRegHi[i] = *(const float4*)(B + (size_t)(k + 1) * 128 + bn);
            }
        }

        // ---- mma over this chunk: 2 k-steps of 16 ----
#pragma unroll
        for (int kk = 0; kk < KC; kk += 16) {
            uint32_t af[2][4];
#pragma unroll
            for (int ti = 0; ti < 2; ti++) {
                int row = wm + 16 * ti + g;
                int col = kk + 2 * t;
                af[ti][0] = *(const uint32_t*)&As[row][col];
                af[ti][1] = *(const uint32_t*)&As[row + 8][col];
                af[ti][2] = *(const uint32_t*)&As[row][col + 8];
                af[ti][3] = *(const uint32_t*)&As[row + 8][col + 8];
            }
            uint32_t bf[8][2];
#pragma unroll
            for (int u = 0; u < 8; u++) {
                int n = wn + 8 * u + g;
                int pb = (kk >> 1) + t;
                bf[u][0] = *(const uint32_t*)&Bs2[pb][n];
                bf[u][1] = *(const uint32_t*)&Bs2[pb + 4][n];
            }
#pragma unroll
            for (int ti = 0; ti < 2; ti++)
#pragma unroll
                for (int u = 0; u < 8; u++) {
                    asm volatile(
                        "mma.sync.aligned.m16n8k16.row.col.f32.f16.f16.f32 "
                        "{%0,%1,%2,%3}, {%4,%5,%6,%7}, {%8,%9}, {%0,%1,%2,%3};\n"
                        : "+f"(acc[ti][u][0]), "+f"(acc[ti][u][1]),
                          "+f"(acc[ti][u][2]), "+f"(acc[ti][u][3])
                        : "r"(af[ti][0]), "r"(af[ti][1]), "r"(af[ti][2]), "r"(af[ti][3]),
                          "r"(bf[u][0]), "r"(bf[u][1]));
                }
        }
        __syncthreads();
    }

#pragma unroll
    for (int ti = 0; ti < 2; ti++) {
        int row0 = block_row + wm + 16 * ti + g;
        int row1 = row0 + 8;
        float sc0 = (row0 < M) ? rowscale[row0] : 0.f;
        float sc1 = (row1 < M) ? rowscale[row1] : 0.f;
#pragma unroll
        for (int u = 0; u < 8; u++) {
            int cb = wn + 8 * u + 2 * t;
            if (row0 < M)
                *(__half2*)(C + (size_t)row0 * 128 + cb) =
                    __floats2half2_rn(acc[ti][u][0] * sc0, acc[ti][u][1] * sc0);
            if (row1 < M)
                *(__half2*)(C + (size_t)row1 * 128 + cb) =
                    __floats2half2_rn(acc[ti][u][2] * sc1, acc[ti][u][3] * sc1);
        }
    }
}

// ---------------------------------------------------------------------------
// Gather: CSR row sum over fp16 features, fp32 accumulation, 4-edge MLP unroll
// ---------------------------------------------------------------------------
__device__ __forceinline__ void csr_rowsum_h(const int* __restrict__ rp,
                                             const int* __restrict__ col,
                                             const __half* __restrict__ feat,
                                             int r, int lo, float4& acc) {
    acc = make_float4(0.f, 0.f, 0.f, 0.f);
    int j = rp[r], e = rp[r + 1];
    for (; j + 3 < e; j += 4) {
        int s0 = col[j], s1 = col[j + 1], s2 = col[j + 2], s3 = col[j + 3];
        uint2 u0 = *(const uint2*)(feat + (size_t)s0 * FD + lo);
        uint2 u1 = *(const uint2*)(feat + (size_t)s1 * FD + lo);
        uint2 u2 = *(const uint2*)(feat + (size_t)s2 * FD + lo);
        uint2 u3 = *(const uint2*)(feat + (size_t)s3 * FD + lo);
        float2 a0 = __half22float2(*(__half2*)&u0.x), b0 = __half22float2(*(__half2*)&u0.y);
        float2 a1 = __half22float2(*(__half2*)&u1.x), b1 = __half22float2(*(__half2*)&u1.y);
        float2 a2 = __half22float2(*(__half2*)&u2.x), b2 = __half22float2(*(__half2*)&u2.y);
        float2 a3 = __half22float2(*(__half2*)&u3.x), b3 = __half22float2(*(__half2*)&u3.y);
        acc.x += (a0.x + a1.x) + (a2.x + a3.x);
        acc.y += (a0.y + a1.y) + (a2.y + a3.y);
        acc.z += (b0.x + b1.x) + (b2.x + b3.x);
        acc.w += (b0.y + b1.y) + (b2.y + b3.y);
    }
    for (; j < e; j++) {
        int s0 = col[j];
        uint2 u0 = *(const uint2*)(feat + (size_t)s0 * FD + lo);
        float2 a0 = __half22float2(*(__half2*)&u0.x), b0 = __half22float2(*(__half2*)&u0.y);
        acc.x += a0.x; acc.y += a0.y; acc.z += b0.x; acc.w += b0.y;
    }
}

// Layer-1 fused gather: chem rows (two relations, relu, fp16 out)
//                     + gene rows (one relation, relu, fp16 out)
__global__ __launch_bounds__(256) void gather_l1(
    const int* __restrict__ rpA, const int* __restrict__ colA,
    const __half* __restrict__ featA, const float* __restrict__ invdA,
    const float* __restrict__ bA,
    const int* __restrict__ rpB, const int* __restrict__ colB,
    const __half* __restrict__ featB, const float* __restrict__ invdB,
    const float* __restrict__ bB,
    __half* __restrict__ outC, int Nc,
    const int* __restrict__ rpG, const int* __restrict__ colG,
    const __half* __restrict__ featG, const float* __restrict__ invdG,
    const float* __restrict__ bG,
    __half* __restrict__ outG, int Ng) {
    int r = blockIdx.x * 8 + (threadIdx.x >> 5);
    int lane = threadIdx.x & 31;
    int lo = lane * 4;
    float4 res;
    __half* optr;
    if (r < Nc) {
        float4 a, b;
        csr_rowsum_h(rpA, colA, featA, r, lo, a);
        csr_rowsum_h(rpB, colB, featB, r, lo, b);
        float wa = invdA[r], wb = invdB[r];
        float4 ba = *(const float4*)(bA + lo);
        float4 bb = *(const float4*)(bB + lo);
        res = make_float4(a.x * wa + b.x * wb + ba.x + bb.x,
                          a.y * wa + b.y * wb + ba.y + bb.y,
                          a.z * wa + b.z * wb + ba.z + bb.z,
                          a.w * wa + b.w * wb + ba.w + bb.w);
        optr = outC + (size_t)r * FD + lo;
    } else if (r < Nc + Ng) {
        int rg = r - Nc;
        float4 a;
        csr_rowsum_h(rpG, colG, featG, rg, lo, a);
        float w = invdG[rg];
        float4 bb = *(const float4*)(bG + lo);
        res = make_float4(a.x * w + bb.x, a.y * w + bb.y,
                          a.z * w + bb.z, a.w * w + bb.w);
        optr = outG + (size_t)rg * FD + lo;
    } else {
        return;
    }
    res.x = res.x > 0.f ? res.x : 0.01f * res.x;
    res.y = res.y > 0.f ? res.y : 0.01f * res.y;
    res.z = res.z > 0.f ? res.z : 0.01f * res.z;
    res.w = res.w > 0.f ? res.w : 0.01f * res.w;
    *(__half2*)(optr + 0) = __floats2half2_rn(res.x, res.y);
    *(__half2*)(optr + 2) = __floats2half2_rn(res.z, res.w);
}

// Layer-2 gather: chem rows, two relations, fp32 out, no relu
__global__ __launch_bounds__(256) void gather_l2(
    const int* __restrict__ rpA, const int* __restrict__ colA,
    const __half* __restrict__ featA, const float* __restrict__ invdA,
    const float* __restrict__ bA,
    const int* __restrict__ rpB, const int* __restrict__ colB,
    const __half* __restrict__ featB, const float* __restrict__ invdB,
    const float* __restrict__ bB,
    float* __restrict__ out, int rows) {
    int r = blockIdx.x * 8 + (threadIdx.x >> 5);
    if (r >= rows) return;
    int lane = threadIdx.x & 31;
    int lo = lane * 4;
    float4 a, b;
    csr_rowsum_h(rpA, colA, featA, r, lo, a);
    csr_rowsum_h(rpB, colB, featB, r, lo, b);
    float wa = invdA[r], wb = invdB[r];
    float4 ba = *(const float4*)(bA + lo);
    float4 bb = *(const float4*)(bB + lo);
    float4 res = make_float4(a.x * wa + b.x * wb + ba.x + bb.x,
                             a.y * wa + b.y * wb + ba.y + bb.y,
                             a.z * wa + b.z * wb + ba.z + bb.z,
                             a.w * wa + b.w * wb + ba.w + bb.w);
    *(float4*)(out + (size_t)r * FD + lo) = res;
}

// ---------------------------------------------------------------------------
// Host launch
// ---------------------------------------------------------------------------
extern "C" void kernel_launch(void* const* d_in, const int* in_sizes, int n_in,
                              void* d_out, int out_size) {
    const float* x_chem = (const float*)d_in[0];
    const float* x_gene = (const float*)d_in[1];
    const int* src_cc = (const int*)d_in[2];
    const int* dst_cc = (const int*)d_in[3];
    const int* src_cg = (const int*)d_in[4];
    const int* dst_cg = (const int*)d_in[5];
    const int* src_gc = (const int*)d_in[6];
    const int* dst_gc = (const int*)d_in[7];

    const float *W1_cc, *W1_cg, *W1_gc, *W2_cc, *W2_cg, *W2_gc;
    const float *b1_cc, *b1_cg, *b1_gc, *b2_cc, *b2_cg, *b2_gc;
    if (in_sizes[9] == FD) {  // interleaved
        W1_cc = (const float*)d_in[8];  b1_cc = (const float*)d_in[9];
        W1_cg = (const float*)d_in[10]; b1_cg = (const float*)d_in[11];
        W1_gc = (const float*)d_in[12]; b1_gc = (const float*)d_in[13];
        W2_cc = (const float*)d_in[14]; b2_cc = (const float*)d_in[15];
        W2_cg = (const float*)d_in[16]; b2_cg = (const float*)d_in[17];
        W2_gc = (const float*)d_in[18]; b2_gc = (const float*)d_in[19];
    } else {                  // grouped
        W1_cc = (const float*)d_in[8];
        W1_cg = (const float*)d_in[9];
        W1_gc = (const float*)d_in[10];
        W2_cc = (const float*)d_in[11];
        W2_cg = (const float*)d_in[12];
        W2_gc = (const float*)d_in[13];
        b1_cc = (const float*)d_in[14];
        b1_cg = (const float*)d_in[15];
        b1_gc = (const float*)d_in[16];
        b2_cc = (const float*)d_in[17];
        b2_cg = (const float*)d_in[18];
        b2_gc = (const float*)d_in[19];
    }

    int Nc = in_sizes[0] / FD;
    int Ng = in_sizes[1] / FD;
    int nEcc = in_sizes[2];
    int nEcg = in_sizes[4];
    int nEgc = in_sizes[6];

    __half* hs = nullptr;
    float* deg = nullptr;
    int* ints = nullptr;
    cudaGetSymbolAddress((void**)&hs, g_hscratch);
    cudaGetSymbolAddress((void**)&deg, g_deg);
    cudaGetSymbolAddress((void**)&ints, g_int);

    __half* Ycc = hs + HOFF_YCC;
    __half* Ycg = hs + HOFF_YCG;
    __half* Ygc = hs + HOFF_YGC;
    __half* h1c = hs + HOFF_H1C;
    __half* h1g = hs + HOFF_H1G;

    float* invs_cc = deg + DOFF_INVS_CC;
    float* invs_cg = deg + DOFF_INVS_CG;
    float* invs_gc = deg + DOFF_INVS_GC;
    float* invd_cc = deg + DOFF_INVD_CC;
    float* invd_gc = deg + DOFF_INVD_GC;
    float* invd_cg = deg + DOFF_INVD_CG;

    int* rp_cc = ints + IOFF_RP_CC;
    int* cur_cc = ints + IOFF_CUR_CC;
    int* rp_gc = ints + IOFF_RP_GC;
    int* cur_gc = ints + IOFF_CUR_GC;
    int* rp_cg = ints + IOFF_RP_CG;
    int* cur_cg = ints + IOFF_CUR_CG;
    int* col_cc = ints + IOFF_COL_CC;
    int* col_gc = ints + IOFF_COL_GC;
    int* col_cg = ints + IOFF_COL_CG;
    int* bsum = ints + IOFF_BSUM;

    float* out = (float*)d_out;

    // ---- degrees ----
    cudaMemsetAsync(deg, 0, DEG_TOTAL * sizeof(float), 0);
    int nEtot = nEcc + nEcg + nEgc;
    deg_all<<<(nEtot + 255) / 256, 256>>>(src_cc, dst_cc, nEcc, invs_cc, invd_cc,
                                          src_cg, dst_cg, nEcg, invs_cg, invd_cg,
                                          src_gc, dst_gc, nEgc, invs_gc, invd_gc);

    // ---- CSR scan (+ fused rsqrt) ----
    int nb0 = (Nc + SCAN_TILE - 1) / SCAN_TILE;
    int nb1 = (Nc + SCAN_TILE - 1) / SCAN_TILE;
    int nb2 = (Ng + SCAN_TILE - 1) / SCAN_TILE;
    int nbT = nb0 + nb1 + nb2;
    int nrs = (INVS_TOTAL + SCAN_TILE - 1) / SCAN_TILE;
    scan_pass1<<<nbT, 256>>>(invd_cc, Nc, invd_gc, Nc, invd_cg, Ng, nb0, nb1, bsum);
    scan_pass2<<<1, 32>>>(bsum, nb0, nb1, nb2, rp_cc, Nc, rp_gc, Nc, rp_cg, Ng);
    scan_pass3<<<nbT + nrs, 256>>>(invd_cc, Nc, rp_cc, cur_cc,
                                   invd_gc, Nc, rp_gc, cur_gc,
                                   invd_cg, Ng, rp_cg, cur_cg,
                                   nb0, nb1, nbT, bsum,
                                   deg, INVS_TOTAL);
    fill_all<<<(nEtot + 255) / 256, 256>>>(src_cc, dst_cc, nEcc, cur_cc, col_cc,
                                           src_gc, dst_gc, nEgc, cur_gc, col_gc,
                                           src_cg, dst_cg, nEcg, cur_cg, col_cg);

    // ---- layer 1: all three GEMMs in one grid (fp32 in -> fp16 mma -> fp16 out) ----
    int gBlkC = (Nc + 127) / 128;
    int gBlkG = (Ng + 127) / 128;
    sgemm_h16_3<0><<<2 * gBlkC + gBlkG, 256>>>(
        x_chem, W1_cc, invs_cc, Ycc, Nc, gBlkC,
        x_chem, W1_cg, invs_cg, Ycg, Nc, gBlkC,
        x_gene, W1_gc, invs_gc, Ygc, Ng);

    // ---- layer 1: fused gathers ----
    gather_l1<<<(Nc + Ng + 7) / 8, 256>>>(rp_cc, col_cc, Ycc, invd_cc, b1_cc,
                                          rp_gc, col_gc, Ygc, invd_gc, b1_gc,
                                          h1c, Nc,
                                          rp_cg, col_cg, Ycg, invd_cg, b1_cg,
                                          h1g, Ng);

    // ---- layer 2: both GEMMs in one grid (fp16 in, fp16 out) ----
    sgemm_h16_3<1><<<gBlkC + gBlkG, 256>>>(
        h1c, W2_cc, invs_cc, Ycc, Nc, gBlkC,
        h1g, W2_gc, invs_gc, Ygc, Ng, gBlkG,
        (const void*)nullptr, (const float*)nullptr, (const float*)nullptr,
        (__half*)nullptr, 0);

    // ---- layer 2: gather -> fp32 output ----
    gather_l2<<<(Nc + 7) / 8, 256>>>(rp_cc, col_cc, Ycc, invd_cc, b2_cc,
                                     rp_gc, col_gc, Ygc, invd_gc, b2_gc,
                                     out, Nc);
}

// round 7
// speedup vs baseline: 5.9299x; 1.1547x over previous
#include <cuda_runtime.h>
#include <cuda_fp16.h>
#include <cstdint>

// ---------------------------------------------------------------------------
// Problem constants
// ---------------------------------------------------------------------------
#define NC_MAX 50000
#define NG_MAX 30000
#define FD 128
#define ECC_MAX 500000
#define ECG_MAX 400000
#define EGC_MAX 400000

// fp16 feature scratch
#define HOFF_YCC ((size_t)0)
#define HOFF_YCG ((size_t)NC_MAX * FD)
#define HOFF_YGC ((size_t)2 * NC_MAX * FD)
#define HOFF_H1C (HOFF_YGC + (size_t)NG_MAX * FD)
#define HOFF_H1G (HOFF_H1C + (size_t)NC_MAX * FD)
#define HSCRATCH_TOTAL (HOFF_H1G + (size_t)NG_MAX * FD)

__device__ __align__(16) __half g_hscratch[HSCRATCH_TOTAL];

// Degree arrays + scan descriptors (all zeroed by one memset).
// Layout: [invs_cc | invs_cg | invs_gc | invd_cc | invd_gc | invd_cg | desc(256)]
#define DOFF_INVS_CC 0
#define DOFF_INVS_CG (DOFF_INVS_CC + NC_MAX)
#define DOFF_INVS_GC (DOFF_INVS_CG + NC_MAX)
#define INVS_TOTAL   (DOFF_INVS_GC + NG_MAX)
#define DOFF_INVD_CC (INVS_TOTAL)
#define DOFF_INVD_GC (DOFF_INVD_CC + NC_MAX)
#define DOFF_INVD_CG (DOFF_INVD_GC + NC_MAX)
#define DOFF_DESC    (DOFF_INVD_CG + NG_MAX)
#define DEG_TOTAL    (DOFF_DESC + 256)

__device__ float g_deg[DEG_TOTAL];

// Int scratch
#define IOFF_RP_CC  0
#define IOFF_CUR_CC (IOFF_RP_CC + NC_MAX + 1)
#define IOFF_RP_GC  (IOFF_CUR_CC + NC_MAX)
#define IOFF_CUR_GC (IOFF_RP_GC + NC_MAX + 1)
#define IOFF_RP_CG  (IOFF_CUR_GC + NC_MAX)
#define IOFF_CUR_CG (IOFF_RP_CG + NG_MAX + 1)
#define IOFF_COL_CC (IOFF_CUR_CG + NG_MAX)
#define IOFF_COL_GC (IOFF_COL_CC + ECC_MAX)
#define IOFF_COL_CG (IOFF_COL_GC + EGC_MAX)
#define INT_TOTAL   (IOFF_COL_CG + ECG_MAX)

__device__ int g_int[INT_TOTAL];

// ---------------------------------------------------------------------------
// Degree histogram: all 3 relations in one launch
// ---------------------------------------------------------------------------
__global__ void deg_all(const int* __restrict__ s0, const int* __restrict__ d0, int n0,
                        float* dS0, float* dD0,
                        const int* __restrict__ s1, const int* __restrict__ d1, int n1,
                        float* dS1, float* dD1,
                        const int* __restrict__ s2, const int* __restrict__ d2, int n2,
                        float* dS2, float* dD2) {
    int i = blockIdx.x * blockDim.x + threadIdx.x;
    if (i < n0) {
        atomicAdd(&dS0[s0[i]], 1.0f);
        atomicAdd(&dD0[d0[i]], 1.0f);
    } else if (i < n0 + n1) {
        int j = i - n0;
        atomicAdd(&dS1[s1[j]], 1.0f);
        atomicAdd(&dD1[d1[j]], 1.0f);
    } else if (i < n0 + n1 + n2) {
        int j = i - n0 - n1;
        atomicAdd(&dS2[s2[j]], 1.0f);
        atomicAdd(&dD2[d2[j]], 1.0f);
    }
}

// ---------------------------------------------------------------------------
// Single-kernel decoupled-lookback exclusive scan over 3 relations.
// Produces rowptr/cursor, rewrites in-degree counts to rsqrt (invd),
// extra blocks rsqrt the out-degree (invs) region.
// desc[]: per-block packed {status[31:30], value[29:0]}, pre-zeroed.
// ---------------------------------------------------------------------------
#define SCAN_TILE 1024
#define SFLAG_A (1 << 30)
#define SFLAG_P (2 << 30)
#define SVALM   0x3FFFFFFF

__global__ __launch_bounds__(256) void scan_fused(
    float* c0, int n0, int* rp0, int* cur0,
    float* c1, int n1, int* rp1, int* cur1,
    float* c2, int n2, int* rp2, int* cur2,
    int nb0, int nb1, int nbT, int* desc,
    float* invs_region, int invs_n) {
    int gb = blockIdx.x;
    if (gb >= nbT) {  // rsqrt of out-degree region
        int base = (gb - nbT) * SCAN_TILE + threadIdx.x * 4;
#pragma unroll
        for (int j = 0; j < 4; j++) {
            int i = base + j;
            if (i < invs_n) invs_region[i] = rsqrtf(fmaxf(invs_region[i], 1.0f));
        }
        return;
    }
    float* cnt; int n, lb, dbase, nbRel; int* rp; int* cur;
    if (gb < nb0) { cnt = c0; n = n0; lb = gb; dbase = 0; nbRel = nb0; rp = rp0; cur = cur0; }
    else if (gb < nb0 + nb1) { cnt = c1; n = n1; lb = gb - nb0; dbase = nb0; nbRel = nb1; rp = rp1; cur = cur1; }
    else { cnt = c2; n = n2; lb = gb - nb0 - nb1; dbase = nb0 + nb1; nbRel = nbT - nb0 - nb1; rp = rp2; cur = cur2; }

    int tid = threadIdx.x, lane = tid & 31, w = tid >> 5;
    int base = lb * SCAN_TILE + tid * 4;
    int v[4];
    int s = 0;
#pragma unroll
    for (int j = 0; j < 4; j++) {
        int i = base + j;
        v[j] = (i < n) ? (int)cnt[i] : 0;
        s += v[j];
    }
    // intra-warp inclusive scan of per-thread sums
    int x = s;
#pragma unroll
    for (int o = 1; o < 32; o <<= 1) {
        int y = __shfl_up_sync(0xffffffffu, x, o);
        if (lane >= o) x += y;
    }
    __shared__ int ws[8];
    __shared__ int s_run;
    if (lane == 31) ws[w] = x;
    __syncthreads();

    if (w == 0) {
        // warp 0: scan the 8 warp sums, compute block total, do lookback
        int wv = (lane < 8) ? ws[lane] : 0;
        int wx = wv;
#pragma unroll
        for (int o = 1; o < 8; o <<= 1) {
            int y = __shfl_up_sync(0xffffffffu, wx, o);
            if (lane >= o) wx += y;
        }
        if (lane < 8) ws[lane] = wx - wv;  // exclusive warp offsets
        int tot = __shfl_sync(0xffffffffu, wx, 7);

        int running = 0;
        if (lb > 0) {
            if (lane == 0) atomicExch(&desc[dbase + lb], SFLAG_A | tot);
            int j = lb - 1;
            while (true) {
                int idx = j - lane;
                int p = 0;
                if (idx >= 0) {
                    volatile int* dp = (volatile int*)(desc + dbase + idx);
                    do { p = *dp; } while ((p & (SFLAG_A | SFLAG_P)) == 0);
                }
                unsigned pm = __ballot_sync(0xffffffffu, idx >= 0 && (p & SFLAG_P));
                int contrib;
                if (pm) {
                    int firstP = __ffs(pm) - 1;
                    contrib = (idx >= 0 && lane <= firstP) ? (p & SVALM) : 0;
                } else {
                    contrib = (idx >= 0) ? (p & SVALM) : 0;
                }
#pragma unroll
                for (int o = 16; o; o >>= 1) contrib += __shfl_down_sync(0xffffffffu, contrib, o);
                contrib = __shfl_sync(0xffffffffu, contrib, 0);
                running += contrib;
                if (pm) break;
                j -= 32;
            }
        }
        if (lane == 0) {
            atomicExch(&desc[dbase + lb], SFLAG_P | (running + tot));
            s_run = running;
            if (lb == nbRel - 1) rp[n] = running + tot;
        }
    }
    __syncthreads();

    int excl = s_run + ws[w] + (x - s);
#pragma unroll
    for (int j = 0; j < 4; j++) {
        int i = base + j;
        if (i < n) {
            rp[i] = excl;
            cur[i] = excl;
            cnt[i] = rsqrtf(fmaxf((float)v[j], 1.0f));  // becomes invd
        }
        excl += v[j];
    }
}

// CSR fill: all 3 relations in one launch
__global__ void fill_all(const int* __restrict__ s0, const int* __restrict__ d0, int n0,
                         int* cur0, int* col0,
                         const int* __restrict__ s1, const int* __restrict__ d1, int n1,
                         int* cur1, int* col1,
                         const int* __restrict__ s2, const int* __restrict__ d2, int n2,
                         int* cur2, int* col2) {
    int i = blockIdx.x * blockDim.x + threadIdx.x;
    if (i < n0) {
        int p = atomicAdd(&cur0[d0[i]], 1);
        col0[p] = s0[i];
    } else if (i < n0 + n1) {
        int j = i - n0;
        int p = atomicAdd(&cur1[d1[j]], 1);
        col1[p] = s1[j];
    } else if (i < n0 + n1 + n2) {
        int j = i - n0 - n1;
        int p = atomicAdd(&cur2[d2[j]], 1);
        col2[p] = s2[j];
    }
}

// ---------------------------------------------------------------------------
// FP16 tensor-core GEMM (m16n8k16), 3 segments, double-buffered smem
// (one __syncthreads per K-chunk).
// ---------------------------------------------------------------------------
#define KC 32

template <int IN_HALF>
__global__ __launch_bounds__(256) void sgemm_h16_3(
    const void* A0, const float* B0, const float* s0, __half* C0, int M0, int nb0,
    const void* A1, const float* B1, const float* s1, __half* C1, int M1, int nb1,
    const void* A2, const float* B2, const float* s2, __half* C2, int M2) {
    __shared__ __half As[2][128][40];
    __shared__ __half2 Bs2[2][KC / 2][136];

    const void* A;
    const float *B, *rowscale;
    __half* C;
    int M, lb;
    int b = blockIdx.x;
    if (b < nb0) { A = A0; B = B0; rowscale = s0; C = C0; M = M0; lb = b; }
    else if (b < nb0 + nb1) { A = A1; B = B1; rowscale = s1; C = C1; M = M1; lb = b - nb0; }
    else { A = A2; B = B2; rowscale = s2; C = C2; M = M2; lb = b - nb0 - nb1; }

    int tid = threadIdx.x;
    int warp = tid >> 5, lane = tid & 31;
    int wm = (warp >> 1) * 32;
    int wn = (warp & 1) * 64;
    int g = lane >> 2;
    int t = lane & 3;
    int block_row = lb * 128;

    float acc[2][8][4];
#pragma unroll
    for (int i = 0; i < 2; i++)
#pragma unroll
        for (int j = 0; j < 8; j++)
#pragma unroll
            for (int k = 0; k < 4; k++) acc[i][j][k] = 0.0f;

    int ar = tid >> 3;
    int ac = (tid & 7) * 4;
    int kp = tid >> 5;
    int bn = (tid & 31) * 4;

    float4 aReg[4];
    uint2 aRegH[4];
    float4 bRegLo[2], bRegHi[2];

    // ---- load + store chunk 0 ----
#pragma unroll
    for (int i = 0; i < 4; i++) {
        int gr = block_row + ar + 32 * i;
        if (IN_HALF) {
            aRegH[i] = make_uint2(0u, 0u);
            if (gr < M) aRegH[i] = *(const uint2*)((const __half*)A + (size_t)gr * 128 + ac);
        } else {
            aReg[i] = make_float4(0.f, 0.f, 0.f, 0.f);
            if (gr < M) aReg[i] = *(const float4*)((const float*)A + (size_t)gr * 128 + ac);
        }
    }
#pragma unroll
    for (int i = 0; i < 2; i++) {
        int k = 2 * (kp + 8 * i);
        bRegLo[i] = *(const float4*)(B + (size_t)k * 128 + bn);
        bRegHi[i] = *(const float4*)(B + (size_t)(k + 1) * 128 + bn);
    }
#pragma unroll
    for (int i = 0; i < 4; i++) {
        int r = ar + 32 * i;
        __half2 h0, h1;
        if (IN_HALF) { h0 = *(__half2*)&aRegH[i].x; h1 = *(__half2*)&aRegH[i].y; }
        else { h0 = __floats2half2_rn(aReg[i].x, aReg[i].y); h1 = __floats2half2_rn(aReg[i].z, aReg[i].w); }
        *(__half2*)&As[0][r][ac + 0] = h0;
        *(__half2*)&As[0][r][ac + 2] = h1;
    }
#pragma unroll
    for (int i = 0; i < 2; i++) {
        int p = kp + 8 * i;
        Bs2[0][p][bn + 0] = __floats2half2_rn(bRegLo[i].x, bRegHi[i].x);
        Bs2[0][p][bn + 1] = __floats2half2_rn(bRegLo[i].y, bRegHi[i].y);
        Bs2[0][p][bn + 2] = __floats2half2_rn(bRegLo[i].z, bRegHi[i].z);
        Bs2[0][p][bn + 3] = __floats2half2_rn(bRegLo[i].w, bRegHi[i].w);
    }
    __syncthreads();

    int st = 0;
    for (int k0 = 0; k0 < 128; k0 += KC, st ^= 1) {
        bool hasNext = (k0 + KC < 128);
        // prefetch next chunk into regs
        if (hasNext) {
#pragma unroll
            for (int i = 0; i < 4; i++) {
                int gr = block_row + ar + 32 * i;
                if (gr < M) {
                    if (IN_HALF)
                        aRegH[i] = *(const uint2*)((const __half*)A + (size_t)gr * 128 + k0 + KC + ac);
                    else
                        aReg[i] = *(const float4*)((const float*)A + (size_t)gr * 128 + k0 + KC + ac);
                }
            }
#pragma unroll
            for (int i = 0; i < 2; i++) {
                int k = k0 + KC + 2 * (kp + 8 * i);
                bRegLo[i] = *(const float4*)(B + (size_t)k * 128 + bn);
                bRegHi[i] = *(const float4*)(B + (size_t)(k + 1) * 128 + bn);
            }
        }

        // mma over current stage
#pragma unroll
        for (int kk = 0; kk < KC; kk += 16) {
            uint32_t af[2][4];
#pragma unroll
            for (int ti = 0; ti < 2; ti++) {
                int row = wm + 16 * ti + g;
                int col = kk + 2 * t;
                af[ti][0] = *(const uint32_t*)&As[st][row][col];
                af[ti][1] = *(const uint32_t*)&As[st][row + 8][col];
                af[ti][2] = *(const uint32_t*)&As[st][row][col + 8];
                af[ti][3] = *(const uint32_t*)&As[st][row + 8][col + 8];
            }
            uint32_t bf[8][2];
#pragma unroll
            for (int u = 0; u < 8; u++) {
                int n = wn + 8 * u + g;
                int pb = (kk >> 1) + t;
                bf[u][0] = *(const uint32_t*)&Bs2[st][pb][n];
                bf[u][1] = *(const uint32_t*)&Bs2[st][pb + 4][n];
            }
#pragma unroll
            for (int ti = 0; ti < 2; ti++)
#pragma unroll
                for (int u = 0; u < 8; u++) {
                    asm volatile(
                        "mma.sync.aligned.m16n8k16.row.col.f32.f16.f16.f32 "
                        "{%0,%1,%2,%3}, {%4,%5,%6,%7}, {%8,%9}, {%0,%1,%2,%3};\n"
                        : "+f"(acc[ti][u][0]), "+f"(acc[ti][u][1]),
                          "+f"(acc[ti][u][2]), "+f"(acc[ti][u][3])
                        : "r"(af[ti][0]), "r"(af[ti][1]), "r"(af[ti][2]), "r"(af[ti][3]),
                          "r"(bf[u][0]), "r"(bf[u][1]));
                }
        }

        // store next chunk into other stage, then single sync
        if (hasNext) {
#pragma unroll
            for (int i = 0; i < 4; i++) {
                int r = ar + 32 * i;
                __half2 h0, h1;
                if (IN_HALF) { h0 = *(__half2*)&aRegH[i].x; h1 = *(__half2*)&aRegH[i].y; }
                else { h0 = __floats2half2_rn(aReg[i].x, aReg[i].y); h1 = __floats2half2_rn(aReg[i].z, aReg[i].w); }
                *(__half2*)&As[st ^ 1][r][ac + 0] = h0;
                *(__half2*)&As[st ^ 1][r][ac + 2] = h1;
            }
#pragma unroll
            for (int i = 0; i < 2; i++) {
                int p = kp + 8 * i;
                Bs2[st ^ 1][p][bn + 0] = __floats2half2_rn(bRegLo[i].x, bRegHi[i].x);
                Bs2[st ^ 1][p][bn + 1] = __floats2half2_rn(bRegLo[i].y, bRegHi[i].y);
                Bs2[st ^ 1][p][bn + 2] = __floats2half2_rn(bRegLo[i].z, bRegHi[i].z);
                Bs2[st ^ 1][p][bn + 3] = __floats2half2_rn(bRegLo[i].w, bRegHi[i].w);
            }
            __syncthreads();
        }
    }

#pragma unroll
    for (int ti = 0; ti < 2; ti++) {
        int row0 = block_row + wm + 16 * ti + g;
        int row1 = row0 + 8;
        float sc0 = (row0 < M) ? rowscale[row0] : 0.f;
        float sc1 = (row1 < M) ? rowscale[row1] : 0.f;
#pragma unroll
        for (int u = 0; u < 8; u++) {
            int cb = wn + 8 * u + 2 * t;
            if (row0 < M)
                *(__half2*)(C + (size_t)row0 * 128 + cb) =
                    __floats2half2_rn(acc[ti][u][0] * sc0, acc[ti][u][1] * sc0);
            if (row1 < M)
                *(__half2*)(C + (size_t)row1 * 128 + cb) =
                    __floats2half2_rn(acc[ti][u][2] * sc1, acc[ti][u][3] * sc1);
        }
    }
}

// ---------------------------------------------------------------------------
// Gather: CSR row sum over fp16 features, fp32 accumulation, 4-edge MLP unroll
// ---------------------------------------------------------------------------
__device__ __forceinline__ void csr_rowsum_h(const int* __restrict__ rp,
                                             const int* __restrict__ col,
                                             const __half* __restrict__ feat,
                                             int r, int lo, float4& acc) {
    acc = make_float4(0.f, 0.f, 0.f, 0.f);
    int j = rp[r], e = rp[r + 1];
    for (; j + 3 < e; j += 4) {
        int s0 = col[j], s1 = col[j + 1], s2 = col[j + 2], s3 = col[j + 3];
        uint2 u0 = *(const uint2*)(feat + (size_t)s0 * FD + lo);
        uint2 u1 = *(const uint2*)(feat + (size_t)s1 * FD + lo);
        uint2 u2 = *(const uint2*)(feat + (size_t)s2 * FD + lo);
        uint2 u3 = *(const uint2*)(feat + (size_t)s3 * FD + lo);
        float2 a0 = __half22float2(*(__half2*)&u0.x), b0 = __half22float2(*(__half2*)&u0.y);
        float2 a1 = __half22float2(*(__half2*)&u1.x), b1 = __half22float2(*(__half2*)&u1.y);
        float2 a2 = __half22float2(*(__half2*)&u2.x), b2 = __half22float2(*(__half2*)&u2.y);
        float2 a3 = __half22float2(*(__half2*)&u3.x), b3 = __half22float2(*(__half2*)&u3.y);
        acc.x += (a0.x + a1.x) + (a2.x + a3.x);
        acc.y += (a0.y + a1.y) + (a2.y + a3.y);
        acc.z += (b0.x + b1.x) + (b2.x + b3.x);
        acc.w += (b0.y + b1.y) + (b2.y + b3.y);
    }
    for (; j < e; j++) {
        int s0 = col[j];
        uint2 u0 = *(const uint2*)(feat + (size_t)s0 * FD + lo);
        float2 a0 = __half22float2(*(__half2*)&u0.x), b0 = __half22float2(*(__half2*)&u0.y);
        acc.x += a0.x; acc.y += a0.y; acc.z += b0.x; acc.w += b0.y;
    }
}

__global__ __launch_bounds__(256) void gather_l1(
    const int* __restrict__ rpA, const int* __restrict__ colA,
    const __half* __restrict__ featA, const float* __restrict__ invdA,
    const float* __restrict__ bA,
    const int* __restrict__ rpB, const int* __restrict__ colB,
    const __half* __restrict__ featB, const float* __restrict__ invdB,
    const float* __restrict__ bB,
    __half* __restrict__ outC, int Nc,
    const int* __restrict__ rpG, const int* __restrict__ colG,
    const __half* __restrict__ featG, const float* __restrict__ invdG,
    const float* __restrict__ bG,
    __half* __restrict__ outG, int Ng) {
    int r = blockIdx.x * 8 + (threadIdx.x >> 5);
    int lane = threadIdx.x & 31;
    int lo = lane * 4;
    float4 res;
    __half* optr;
    if (r < Nc) {
        float4 a, b;
        csr_rowsum_h(rpA, colA, featA, r, lo, a);
        csr_rowsum_h(rpB, colB, featB, r, lo, b);
        float wa = invdA[r], wb = invdB[r];
        float4 ba = *(const float4*)(bA + lo);
        float4 bb = *(const float4*)(bB + lo);
        res = make_float4(a.x * wa + b.x * wb + ba.x + bb.x,
                          a.y * wa + b.y * wb + ba.y + bb.y,
                          a.z * wa + b.z * wb + ba.z + bb.z,
                          a.w * wa + b.w * wb + ba.w + bb.w);
        optr = outC + (size_t)r * FD + lo;
    } else if (r < Nc + Ng) {
        int rg = r - Nc;
        float4 a;
        csr_rowsum_h(rpG, colG, featG, rg, lo, a);
        float w = invdG[rg];
        float4 bb = *(const float4*)(bG + lo);
        res = make_float4(a.x * w + bb.x, a.y * w + bb.y,
                          a.z * w + bb.z, a.w * w + bb.w);
        optr = outG + (size_t)rg * FD + lo;
    } else {
        return;
    }
    res.x = res.x > 0.f ? res.x : 0.01f * res.x;
    res.y = res.y > 0.f ? res.y : 0.01f * res.y;
    res.z = res.z > 0.f ? res.z : 0.01f * res.z;
    res.w = res.w > 0.f ? res.w : 0.01f * res.w;
    *(__half2*)(optr + 0) = __floats2half2_rn(res.x, res.y);
    *(__half2*)(optr + 2) = __floats2half2_rn(res.z, res.w);
}

__global__ __launch_bounds__(256) void gather_l2(
    const int* __restrict__ rpA, const int* __restrict__ colA,
    const __half* __restrict__ featA, const float* __restrict__ invdA,
    const float* __restrict__ bA,
    const int* __restrict__ rpB, const int* __restrict__ colB,
    const __half* __restrict__ featB, const float* __restrict__ invdB,
    const float* __restrict__ bB,
    float* __restrict__ out, int rows) {
    int r = blockIdx.x * 8 + (threadIdx.x >> 5);
    if (r >= rows) return;
    int lane = threadIdx.x & 31;
    int lo = lane * 4;
    float4 a, b;
    csr_rowsum_h(rpA, colA, featA, r, lo, a);
    csr_rowsum_h(rpB, colB, featB, r, lo, b);
    float wa = invdA[r], wb = invdB[r];
    float4 ba = *(const float4*)(bA + lo);
    float4 bb = *(const float4*)(bB + lo);
    float4 res = make_float4(a.x * wa + b.x * wb + ba.x + bb.x,
                             a.y * wa + b.y * wb + ba.y + bb.y,
                             a.z * wa + b.z * wb + ba.z + bb.z,
                             a.w * wa + b.w * wb + ba.w + bb.w);
    *(float4*)(out + (size_t)r * FD + lo) = res;
}

// ---------------------------------------------------------------------------
// Host launch
// ---------------------------------------------------------------------------
extern "C" void kernel_launch(void* const* d_in, const int* in_sizes, int n_in,
                              void* d_out, int out_size) {
    const float* x_chem = (const float*)d_in[0];
    const float* x_gene = (const float*)d_in[1];
    const int* src_cc = (const int*)d_in[2];
    const int* dst_cc = (const int*)d_in[3];
    const int* src_cg = (const int*)d_in[4];
    const int* dst_cg = (const int*)d_in[5];
    const int* src_gc = (const int*)d_in[6];
    const int* dst_gc = (const int*)d_in[7];

    const float *W1_cc, *W1_cg, *W1_gc, *W2_cc, *W2_cg, *W2_gc;
    const float *b1_cc, *b1_cg, *b1_gc, *b2_cc, *b2_cg, *b2_gc;
    if (in_sizes[9] == FD) {  // interleaved
        W1_cc = (const float*)d_in[8];  b1_cc = (const float*)d_in[9];
        W1_cg = (const float*)d_in[10]; b1_cg = (const float*)d_in[11];
        W1_gc = (const float*)d_in[12]; b1_gc = (const float*)d_in[13];
        W2_cc = (const float*)d_in[14]; b2_cc = (const float*)d_in[15];
        W2_cg = (const float*)d_in[16]; b2_cg = (const float*)d_in[17];
        W2_gc = (const float*)d_in[18]; b2_gc = (const float*)d_in[19];
    } else {                  // grouped
        W1_cc = (const float*)d_in[8];
        W1_cg = (const float*)d_in[9];
        W1_gc = (const float*)d_in[10];
        W2_cc = (const float*)d_in[11];
        W2_cg = (const float*)d_in[12];
        W2_gc = (const float*)d_in[13];
        b1_cc = (const float*)d_in[14];
        b1_cg = (const float*)d_in[15];
        b1_gc = (const float*)d_in[16];
        b2_cc = (const float*)d_in[17];
        b2_cg = (const float*)d_in[18];
        b2_gc = (const float*)d_in[19];
    }

    int Nc = in_sizes[0] / FD;
    int Ng = in_sizes[1] / FD;
    int nEcc = in_sizes[2];
    int nEcg = in_sizes[4];
    int nEgc = in_sizes[6];

    __half* hs = nullptr;
    float* deg = nullptr;
    int* ints = nullptr;
    cudaGetSymbolAddress((void**)&hs, g_hscratch);
    cudaGetSymbolAddress((void**)&deg, g_deg);
    cudaGetSymbolAddress((void**)&ints, g_int);

    __half* Ycc = hs + HOFF_YCC;
    __half* Ycg = hs + HOFF_YCG;
    __half* Ygc = hs + HOFF_YGC;
    __half* h1c = hs + HOFF_H1C;
    __half* h1g = hs + HOFF_H1G;

    float* invs_cc = deg + DOFF_INVS_CC;
    float* invs_cg = deg + DOFF_INVS_CG;
    float* invs_gc = deg + DOFF_INVS_GC;
    float* invd_cc = deg + DOFF_INVD_CC;
    float* invd_gc = deg + DOFF_INVD_GC;
    float* invd_cg = deg + DOFF_INVD_CG;
    int* desc = (int*)(deg + DOFF_DESC);

    int* rp_cc = ints + IOFF_RP_CC;
    int* cur_cc = ints + IOFF_CUR_CC;
    int* rp_gc = ints + IOFF_RP_GC;
    int* cur_gc = ints + IOFF_CUR_GC;
    int* rp_cg = ints + IOFF_RP_CG;
    int* cur_cg = ints + IOFF_CUR_CG;
    int* col_cc = ints + IOFF_COL_CC;
    int* col_gc = ints + IOFF_COL_GC;
    int* col_cg = ints + IOFF_COL_CG;

    float* out = (float*)d_out;

    // ---- zero degrees + scan descriptors (one memset) ----
    cudaMemsetAsync(deg, 0, DEG_TOTAL * sizeof(float), 0);
    int nEtot = nEcc + nEcg + nEgc;
    deg_all<<<(nEtot + 255) / 256, 256>>>(src_cc, dst_cc, nEcc, invs_cc, invd_cc,
                                          src_cg, dst_cg, nEcg, invs_cg, invd_cg,
                                          src_gc, dst_gc, nEgc, invs_gc, invd_gc);

    // ---- single-kernel decoupled-lookback scan (+ fused rsqrt) ----
    int nb0 = (Nc + SCAN_TILE - 1) / SCAN_TILE;
    int nb1 = (Nc + SCAN_TILE - 1) / SCAN_TILE;
    int nb2 = (Ng + SCAN_TILE - 1) / SCAN_TILE;
    int nbT = nb0 + nb1 + nb2;
    int nrs = (INVS_TOTAL + SCAN_TILE - 1) / SCAN_TILE;
    scan_fused<<<nbT + nrs, 256>>>(invd_cc, Nc, rp_cc, cur_cc,
                                   invd_gc, Nc, rp_gc, cur_gc,
                                   invd_cg, Ng, rp_cg, cur_cg,
                                   nb0, nb1, nbT, desc,
                                   deg, INVS_TOTAL);
    fill_all<<<(nEtot + 255) / 256, 256>>>(src_cc, dst_cc, nEcc, cur_cc, col_cc,
                                           src_gc, dst_gc, nEgc, cur_gc, col_gc,
                                           src_cg, dst_cg, nEcg, cur_cg, col_cg);

    // ---- layer 1: all three GEMMs in one grid ----
    int gBlkC = (Nc + 127) / 128;
    int gBlkG = (Ng + 127) / 128;
    sgemm_h16_3<0><<<2 * gBlkC + gBlkG, 256>>>(
        x_chem, W1_cc, invs_cc, Ycc, Nc, gBlkC,
        x_chem, W1_cg, invs_cg, Ycg, Nc, gBlkC,
        x_gene, W1_gc, invs_gc, Ygc, Ng);

    // ---- layer 1: fused gathers ----
    gather_l1<<<(Nc + Ng + 7) / 8, 256>>>(rp_cc, col_cc, Ycc, invd_cc, b1_cc,
                                          rp_gc, col_gc, Ygc, invd_gc, b1_gc,
                                          h1c, Nc,
                                          rp_cg, col_cg, Ycg, invd_cg, b1_cg,
                                          h1g, Ng);

    // ---- layer 2: both GEMMs in one grid ----
    sgemm_h16_3<1><<<gBlkC + gBlkG, 256>>>(
        h1c, W2_cc, invs_cc, Ycc, Nc, gBlkC,
        h1g, W2_gc, invs_gc, Ygc, Ng, gBlkG,
        (const void*)nullptr, (const float*)nullptr, (const float*)nullptr,
        (__half*)nullptr, 0);

    // ---- layer 2: gather -> fp32 output ----
    gather_l2<<<(Nc + 7) / 8, 256>>>(rp_cc, col_cc, Ycc, invd_cc, b2_cc,
                                     rp_gc, col_gc, Ygc, invd_gc, b2_gc,
                                     out, Nc);
}